// round 9
// baseline (speedup 1.0000x reference)
#include <cuda_runtime.h>

#define BB 16
#define TT 12
#define NN 1024
#define EMB 10
#define DIN 21      // 1 + 2*EMB
#define DOUT 64
#define FF 85       // DIN + DOUT
#define KF 170      // CHEB_K * FF
#define OG 128      // 2*DOUT
#define FG 96       // padded spmm-g cols: 85 data + 1 ones + 10 zero pad

// ---------------- device scratch (static, no allocation) ----------------
__device__ float g_cur[BB*TT*NN*DIN];
__device__ float g_Wg[NN*KF*OG];
__device__ float g_bg[NN*OG];
__device__ float g_Wc[NN*KF*DOUT];
__device__ float g_bc[NN*DOUT];
__device__ float g_h[BB*NN*DOUT];
__device__ float g_M[(size_t)BB*NN*NN];
__device__ float g_Yg[BB*NN*FG];
__device__ float g_Yc[BB*NN*DOUT];
__device__ float g_zh[BB*NN*DOUT];
__device__ float g_r [BB*NN*DOUT];
__device__ float g_seq[BB*TT*NN*DOUT];

// ---------------- helpers ----------------
// e^x for x <= 0, poly exp2 (no MUFU). rel err ~1e-7.
__device__ __forceinline__ float fexp_neg(float x) {
    float t = fmaxf(x * 1.4426950408889634f, -125.0f);
    float fi = rintf(t);
    float f = t - fi;
    float p = 1.5403530393381609e-4f;
    p = fmaf(p, f, 1.3333558146428443e-3f);
    p = fmaf(p, f, 9.6181291076284772e-3f);
    p = fmaf(p, f, 5.5504108664821580e-2f);
    p = fmaf(p, f, 2.4022650695910071e-1f);
    p = fmaf(p, f, 6.9314718055994531e-1f);
    p = fmaf(p, f, 1.0f);
    int i = (int)fi;
    return __int_as_float((i + 127) << 23) * p;
}

__device__ __forceinline__ void fma2(unsigned long long& d,
                                     unsigned long long a, unsigned long long b) {
    asm("fma.rn.f32x2 %0, %1, %2, %0;" : "+l"(d) : "l"(a), "l"(b));
}
__device__ __forceinline__ unsigned long long dup2(float a) {
    unsigned long long r;
    asm("mov.b64 %0, {%1, %1};" : "=l"(r) : "f"(a));
    return r;
}
__device__ __forceinline__ float2 unpack2(unsigned long long v) {
    float2 r;
    asm("mov.b64 {%0, %1}, %2;" : "=f"(r.x), "=f"(r.y) : "l"(v));
    return r;
}

// ---------------- one-time prep kernels ----------------
__global__ void k_embed(const float* __restrict__ x, const float* __restrict__ Wtod,
                        const float* __restrict__ btod, const float* __restrict__ Wdow,
                        const float* __restrict__ bdow) {
    int i = blockIdx.x * blockDim.x + threadIdx.x;
    if (i >= BB*TT*NN) return;
    float v   = x[i*3 + 0];
    int   tod = (int)x[i*3 + 1];
    int   dow = (int)x[i*3 + 2];
    float* c = g_cur + (size_t)i * DIN;
    c[0] = v;
    #pragma unroll
    for (int d = 0; d < EMB; d++) c[1 + d]       = Wtod[tod*EMB + d] + btod[d];
    #pragma unroll
    for (int d = 0; d < EMB; d++) c[1 + EMB + d] = Wdow[dow*EMB + d] + bdow[d];
}

__global__ void k_wpool_g(const float* __restrict__ E, const float* __restrict__ pool) {
    long i = (long)blockIdx.x * blockDim.x + threadIdx.x;
    if (i >= (long)NN*KF*OG) return;
    int o  = (int)(i % OG);
    int kf = (int)((i / OG) % KF);
    int n  = (int)(i / ((long)OG*KF));
    float s = 0.f;
    #pragma unroll
    for (int d = 0; d < EMB; d++)
        s += E[n*EMB + d] * pool[((long)d*KF + kf)*OG + o];
    g_Wg[i] = s;
}

__global__ void k_wpool_c(const float* __restrict__ E, const float* __restrict__ pool) {
    long i = (long)blockIdx.x * blockDim.x + threadIdx.x;
    if (i >= (long)NN*KF*DOUT) return;
    int o  = (int)(i % DOUT);
    int kf = (int)((i / DOUT) % KF);
    int n  = (int)(i / ((long)DOUT*KF));
    float s = 0.f;
    #pragma unroll
    for (int d = 0; d < EMB; d++)
        s += E[n*EMB + d] * pool[((long)d*KF + kf)*DOUT + o];
    g_Wc[i] = s;
}

__global__ void k_bpool_g(const float* __restrict__ E, const float* __restrict__ bpool) {
    int i = blockIdx.x * blockDim.x + threadIdx.x;
    if (i >= NN*OG) return;
    int o = i % OG, n = i / OG;
    float s = 0.f;
    #pragma unroll
    for (int d = 0; d < EMB; d++) s += E[n*EMB + d] * bpool[d*OG + o];
    g_bg[i] = s;
}

__global__ void k_bpool_c(const float* __restrict__ E, const float* __restrict__ bpool) {
    int i = blockIdx.x * blockDim.x + threadIdx.x;
    if (i >= NN*DOUT) return;
    int o = i % DOUT, n = i / DOUT;
    float s = 0.f;
    #pragma unroll
    for (int d = 0; d < EMB; d++) s += E[n*EMB + d] * bpool[d*DOUT + o];
    g_bc[i] = s;
}

__global__ void k_hinit(const float* __restrict__ init_state) {
    int i = blockIdx.x * blockDim.x + threadIdx.x;
    if (i < BB*NN*DOUT) g_h[i] = init_state[i];
}

// ---------------- per-step kernels ----------------
// M[b,n,m] = exp(relu(l) - rowmax(relu(l)))  (poly exp, no MUFU)
__global__ void k_adj(int t, const float* __restrict__ E,
                      const float* __restrict__ ne1, const float* __restrict__ ne2) {
    __shared__ float Es[NN*EMB];
    __shared__ float Er[16][EMB];
    __shared__ float sred[16][8];
    __shared__ float rowmax[16];
    int b = blockIdx.y, n0 = blockIdx.x * 16, tid = threadIdx.x;

    for (int idx = tid; idx < NN*EMB; idx += 256) Es[idx] = E[idx];
    if (tid < 16*EMB) {
        int i = tid / EMB, d = tid % EMB;
        float s = ne1[(b*TT + t)*EMB + d] * ne2[(b*TT + t)*EMB + d];
        Er[i][d] = E[(n0 + i)*EMB + d] * s;
    }
    __syncthreads();

    float lmax[16];
    #pragma unroll
    for (int r = 0; r < 16; r++) lmax[r] = 0.f;
    for (int c = 0; c < 4; c++) {
        int m = c * 256 + tid;
        float em[EMB];
        #pragma unroll
        for (int d = 0; d < EMB; d++) em[d] = Es[m*EMB + d];
        #pragma unroll
        for (int r = 0; r < 16; r++) {
            float l = 0.f;
            #pragma unroll
            for (int d = 0; d < EMB; d++) l += em[d] * Er[r][d];
            lmax[r] = fmaxf(lmax[r], l);
        }
    }
    int lane = tid & 31, w = tid >> 5;
    #pragma unroll
    for (int r = 0; r < 16; r++) {
        float v = lmax[r];
        #pragma unroll
        for (int off = 16; off; off >>= 1) v = fmaxf(v, __shfl_xor_sync(0xffffffffu, v, off));
        if (lane == 0) sred[r][w] = v;
    }
    __syncthreads();
    if (tid < 16) {
        float v = sred[tid][0];
        #pragma unroll
        for (int w2 = 1; w2 < 8; w2++) v = fmaxf(v, sred[tid][w2]);
        rowmax[tid] = v;
    }
    __syncthreads();

    for (int c = 0; c < 4; c++) {
        int m = c * 256 + tid;
        float em[EMB];
        #pragma unroll
        for (int d = 0; d < EMB; d++) em[d] = Es[m*EMB + d];
        #pragma unroll
        for (int r = 0; r < 16; r++) {
            float l = 0.f;
            #pragma unroll
            for (int d = 0; d < EMB; d++) l += em[d] * Er[r][d];
            l = fmaxf(l, 0.f);
            g_M[((size_t)(b*NN) + (n0 + r))*NN + m] = fexp_neg(l - rowmax[r]);
        }
    }
}

// Yg[b, n0..n0+63, 0:96] = M[b] @ [cur_t | h | 1 | 0pad]; f32x2 FFMA2 core.
// 128 threads: tx = tid&15 (6 cols each), ty = tid>>4 (8 rows each).
__global__ void k_spmm_g(int t) {
    __shared__ float As[64][33];   // [r][mm], K-chunk 32
    __shared__ float Xs[32][98];   // [mm][col], 96 cols (pad 98, even)
    int b = blockIdx.y, n0 = blockIdx.x * 64, tid = threadIdx.x;
    int tx = tid & 15, ty = tid >> 4;

    unsigned long long acc[8][3];
    #pragma unroll
    for (int i = 0; i < 8; i++)
        #pragma unroll
        for (int j = 0; j < 3; j++) acc[i][j] = 0ull;

    const float* curb = g_cur + (size_t)(b*TT + t) * NN * DIN;
    const float* hb   = g_h   + (size_t)b * NN * DOUT;
    const size_t mrow = (size_t)b * NN + n0;

    for (int m0 = 0; m0 < NN; m0 += 32) {
        __syncthreads();
        #pragma unroll
        for (int k = 0; k < 16; k++) {
            int idx = tid + k * 128;
            int mm = idx & 31, r = idx >> 5;
            As[r][mm] = g_M[(mrow + r) * NN + m0 + mm];
        }
        #pragma unroll
        for (int k = 0; k < 24; k++) {
            int idx = tid + k * 128;
            int mm = idx / 96, f = idx - mm * 96;
            int m = m0 + mm;
            float v;
            if      (f < DIN) v = curb[m*DIN + f];
            else if (f < FF)  v = hb[m*DOUT + (f - DIN)];
            else              v = (f == FF) ? 1.f : 0.f;
            Xs[mm][f] = v;
        }
        __syncthreads();
        #pragma unroll 2
        for (int mm = 0; mm < 32; mm++) {
            unsigned long long xv0 = *(const unsigned long long*)&Xs[mm][tx*6];
            unsigned long long xv1 = *(const unsigned long long*)&Xs[mm][tx*6 + 2];
            unsigned long long xv2 = *(const unsigned long long*)&Xs[mm][tx*6 + 4];
            #pragma unroll
            for (int i = 0; i < 8; i++) {
                unsigned long long a2 = dup2(As[ty*8 + i][mm]);
                fma2(acc[i][0], a2, xv0);
                fma2(acc[i][1], a2, xv1);
                fma2(acc[i][2], a2, xv2);
            }
        }
    }
    #pragma unroll
    for (int i = 0; i < 8; i++) {
        size_t row = ((size_t)b*NN + n0 + ty*8 + i) * FG;
        #pragma unroll
        for (int j = 0; j < 3; j++) {
            float2 v = unpack2(acc[i][j]);
            *(float2*)&g_Yg[row + tx*6 + 2*j] = v;
        }
    }
}

// Yc[b, n0..n0+63, 0:64] = M[b] @ zh
__global__ void k_spmm_c() {
    __shared__ float As[64][33];
    __shared__ float Xs[32][66];
    int b = blockIdx.y, n0 = blockIdx.x * 64, tid = threadIdx.x;
    int tx = tid & 15, ty = tid >> 4;

    unsigned long long acc[8][2];
    #pragma unroll
    for (int i = 0; i < 8; i++) { acc[i][0] = 0ull; acc[i][1] = 0ull; }

    const float* zb = g_zh + (size_t)b * NN * DOUT;
    const size_t mrow = (size_t)b * NN + n0;

    for (int m0 = 0; m0 < NN; m0 += 32) {
        __syncthreads();
        #pragma unroll
        for (int k = 0; k < 16; k++) {
            int idx = tid + k * 128;
            int mm = idx & 31, r = idx >> 5;
            As[r][mm] = g_M[(mrow + r) * NN + m0 + mm];
        }
        #pragma unroll
        for (int k = 0; k < 16; k++) {
            int idx = tid + k * 128;
            int mm = idx >> 6, f = idx & 63;
            Xs[mm][f] = zb[(m0 + mm)*DOUT + f];
        }
        __syncthreads();
        #pragma unroll 2
        for (int mm = 0; mm < 32; mm++) {
            unsigned long long xv0 = *(const unsigned long long*)&Xs[mm][tx*4];
            unsigned long long xv1 = *(const unsigned long long*)&Xs[mm][tx*4 + 2];
            #pragma unroll
            for (int i = 0; i < 8; i++) {
                unsigned long long a2 = dup2(As[ty*8 + i][mm]);
                fma2(acc[i][0], a2, xv0);
                fma2(acc[i][1], a2, xv1);
            }
        }
    }
    #pragma unroll
    for (int i = 0; i < 8; i++) {
        size_t row = ((size_t)b*NN + n0 + ty*8 + i) * DOUT;
        #pragma unroll
        for (int j = 0; j < 2; j++) {
            float2 v = unpack2(acc[i][j]);
            *(float2*)&g_Yc[row + tx*4 + 2*j] = v;
        }
    }
}

// gate FC: one CTA per node n, all 16 batches
__global__ void k_fc_g(int t) {
    __shared__ float xs[16][172];
    __shared__ float Ws[10][128];
    int n = blockIdx.x, tid = threadIdx.x;

    for (int idx = tid; idx < 16*KF; idx += 128) {
        int b = idx / KF, f = idx % KF;
        float v;
        if      (f < DIN) v = g_cur[((size_t)(b*TT + t)*NN + n)*DIN + f];
        else if (f < FF)  v = g_h[((size_t)b*NN + n)*DOUT + (f - DIN)];
        else {
            const float* y = g_Yg + ((size_t)b*NN + n)*FG;
            v = y[f - FF] / y[FF];
        }
        xs[b][f] = v;
    }
    __syncthreads();

    int og = tid & 31, bg = tid >> 5;
    float acc[4][4];
    #pragma unroll
    for (int i = 0; i < 4; i++)
        #pragma unroll
        for (int j = 0; j < 4; j++) acc[i][j] = 0.f;

    const float* Wn = g_Wg + (size_t)n * KF * OG;
    for (int fc = 0; fc < KF; fc += 10) {
        __syncthreads();
        for (int idx = tid; idx < 10*128; idx += 128)
            ((float*)Ws)[idx] = Wn[fc*128 + idx];
        __syncthreads();
        #pragma unroll
        for (int ff = 0; ff < 10; ff++) {
            float xv[4], wv[4];
            #pragma unroll
            for (int i = 0; i < 4; i++) xv[i] = xs[bg*4 + i][fc + ff];
            #pragma unroll
            for (int j = 0; j < 4; j++) wv[j] = Ws[ff][og + 32*j];
            #pragma unroll
            for (int i = 0; i < 4; i++)
                #pragma unroll
                for (int j = 0; j < 4; j++) acc[i][j] += xv[i] * wv[j];
        }
    }
    #pragma unroll
    for (int i = 0; i < 4; i++) {
        #pragma unroll
        for (int j = 0; j < 4; j++) {
            int b = bg*4 + i, o = og + 32*j;
            float v  = acc[i][j] + g_bg[n*OG + o];
            float sg = 1.f / (1.f + __expf(-v));
            size_t base = ((size_t)b*NN + n) * DOUT;
            if (o < DOUT) g_zh[base + o] = sg * g_h[base + o];
            else          g_r[base + (o - DOUT)] = sg;
        }
    }
}

// candidate FC + GRU update
__global__ void k_fc_c(int t) {
    __shared__ float xs[16][172];
    __shared__ float Ws[10][64];
    int n = blockIdx.x, tid = threadIdx.x;

    for (int idx = tid; idx < 16*KF; idx += 128) {
        int b = idx / KF, f = idx % KF;
        float v;
        if      (f < DIN) v = g_cur[((size_t)(b*TT + t)*NN + n)*DIN + f];
        else if (f < FF)  v = g_zh[((size_t)b*NN + n)*DOUT + (f - DIN)];
        else {
            int fp = f - FF;
            float num = (fp < DIN) ? g_Yg[((size_t)b*NN + n)*FG + fp]
                                   : g_Yc[((size_t)b*NN + n)*DOUT + (fp - DIN)];
            v = num / g_Yg[((size_t)b*NN + n)*FG + FF];
        }
        xs[b][f] = v;
    }
    __syncthreads();

    int og = tid & 31, bg = tid >> 5;
    float acc[4][2];
    #pragma unroll
    for (int i = 0; i < 4; i++) { acc[i][0] = 0.f; acc[i][1] = 0.f; }

    const float* Wn = g_Wc + (size_t)n * KF * DOUT;
    for (int fc = 0; fc < KF; fc += 10) {
        __syncthreads();
        for (int idx = tid; idx < 10*64; idx += 128)
            ((float*)Ws)[idx] = Wn[fc*64 + idx];
        __syncthreads();
        #pragma unroll
        for (int ff = 0; ff < 10; ff++) {
            float xv[4], wv[2];
            #pragma unroll
            for (int i = 0; i < 4; i++) xv[i] = xs[bg*4 + i][fc + ff];
            wv[0] = Ws[ff][og]; wv[1] = Ws[ff][og + 32];
            #pragma unroll
            for (int i = 0; i < 4; i++) {
                acc[i][0] += xv[i] * wv[0];
                acc[i][1] += xv[i] * wv[1];
            }
        }
    }
    #pragma unroll
    for (int i = 0; i < 4; i++) {
        #pragma unroll
        for (int j = 0; j < 2; j++) {
            int b = bg*4 + i, o = og + 32*j;
            float hc = tanhf(acc[i][j] + g_bc[n*DOUT + o]);
            size_t base = ((size_t)b*NN + n) * DOUT;
            float r    = g_r[base + o];
            float hold = g_h[base + o];
            float hn   = r * hold + (1.f - r) * hc;
            g_h[base + o] = hn;
            g_seq[((size_t)(b*TT + t)*NN + n)*DOUT + o] = hn;
        }
    }
}

// ---------------- temporal attention ----------------
__global__ void k_attn(const float* __restrict__ WQ, const float* __restrict__ bQ,
                       const float* __restrict__ WK, const float* __restrict__ bK,
                       const float* __restrict__ WV, const float* __restrict__ bV,
                       float* __restrict__ out) {
    __shared__ float xsm[2*TT*65];
    __shared__ float Qs [2*TT*65];
    __shared__ float Ks [2*TT*65];
    __shared__ float Vs [2*TT*65];
    __shared__ float P  [2*TT*TT];

    int b = blockIdx.y, n0 = blockIdx.x * 2;
    int tid = threadIdx.x, ng = tid >> 6, o = tid & 63, n = n0 + ng;

    #pragma unroll
    for (int t = 0; t < TT; t++)
        xsm[(ng*TT + t)*65 + o] = g_seq[((size_t)(b*TT + t)*NN + n)*DOUT + o];
    __syncthreads();

    float q[TT], k[TT], v[TT];
    {
        float bq = __ldg(bQ + o), bk = __ldg(bK + o), bv = __ldg(bV + o);
        #pragma unroll
        for (int t = 0; t < TT; t++) { q[t] = bq; k[t] = bk; v[t] = bv; }
    }
    for (int f = 0; f < 64; f++) {
        float wq = __ldg(WQ + f*64 + o);
        float wk = __ldg(WK + f*64 + o);
        float wv = __ldg(WV + f*64 + o);
        #pragma unroll
        for (int t = 0; t < TT; t++) {
            float xv = xsm[(ng*TT + t)*65 + f];
            q[t] += xv * wq; k[t] += xv * wk; v[t] += xv * wv;
        }
    }
    #pragma unroll
    for (int t = 0; t < TT; t++) {
        Qs[(ng*TT + t)*65 + o] = q[t];
        Ks[(ng*TT + t)*65 + o] = k[t];
        Vs[(ng*TT + t)*65 + o] = v[t];
    }
    __syncthreads();

    for (int p = o; p < TT*TT; p += 64) {
        int t1 = p / TT, s1 = p % TT;
        float s = 0.f;
        #pragma unroll
        for (int f = 0; f < 64; f++)
            s += Qs[(ng*TT + t1)*65 + f] * Ks[(ng*TT + s1)*65 + f];
        P[(ng*TT + t1)*TT + s1] = s * 0.125f;
    }
    __syncthreads();

    if (tid < 2*TT) {
        int ng2 = tid / TT, t1 = tid % TT;
        float* row = P + (ng2*TT + t1)*TT;
        float m = row[0];
        #pragma unroll
        for (int s = 1; s < TT; s++) m = fmaxf(m, row[s]);
        float sum = 0.f;
        #pragma unroll
        for (int s = 0; s < TT; s++) { float e = __expf(row[s] - m); row[s] = e; sum += e; }
        float inv = 1.f / sum;
        #pragma unroll
        for (int s = 0; s < TT; s++) row[s] *= inv;
    }
    __syncthreads();

    #pragma unroll
    for (int t1 = 0; t1 < TT; t1++) {
        float z = 0.f;
        #pragma unroll
        for (int s1 = 0; s1 < TT; s1++)
            z += P[(ng*TT + t1)*TT + s1] * Vs[(ng*TT + s1)*65 + o];
        out[((size_t)(b*TT + t1)*NN + n)*DOUT + o] = z;
    }
}

__global__ void k_hlast(float* __restrict__ out) {
    int i = blockIdx.x * blockDim.x + threadIdx.x;
    if (i < BB*NN*DOUT) out[(size_t)BB*TT*NN*DOUT + i] = g_h[i];
}

// ---------------- launch ----------------
extern "C" void kernel_launch(void* const* d_in, const int* in_sizes, int n_in,
                              void* d_out, int out_size) {
    const int esz[19] = {589824, 1048576, 1920, 1920, 10240, 480, 10, 70, 10,
                         4096, 64, 4096, 64, 4096, 64, 217600, 1280, 108800, 640};
    const float* p[19];
    int used[64];
    for (int i = 0; i < 64; i++) used[i] = 0;
    for (int j = 0; j < 19; j++) {
        p[j] = (j < n_in) ? (const float*)d_in[j] : (const float*)d_in[0];
        for (int i = 0; i < n_in && i < 64; i++) {
            if (!used[i] && in_sizes[i] == esz[j]) { p[j] = (const float*)d_in[i]; used[i] = 1; break; }
        }
    }
    const float* x          = p[0];
    const float* init_state = p[1];
    const float* ne_tod     = p[2];
    const float* ne_dow     = p[3];
    const float* node_emb   = p[4];
    const float* Wtod       = p[5];
    const float* btod       = p[6];
    const float* Wdow       = p[7];
    const float* bdow       = p[8];
    const float* WQ         = p[9];
    const float* bQ         = p[10];
    const float* WK         = p[11];
    const float* bK         = p[12];
    const float* WV         = p[13];
    const float* bV         = p[14];
    const float* Wpool_g    = p[15];
    const float* bpool_g    = p[16];
    const float* Wpool_c    = p[17];
    const float* bpool_c    = p[18];
    float* out = (float*)d_out;

    // prep
    k_embed<<<(BB*TT*NN + 255)/256, 256>>>(x, Wtod, btod, Wdow, bdow);
    k_wpool_g<<<(int)(((long)NN*KF*OG   + 255)/256), 256>>>(node_emb, Wpool_g);
    k_wpool_c<<<(int)(((long)NN*KF*DOUT + 255)/256), 256>>>(node_emb, Wpool_c);
    k_bpool_g<<<(NN*OG   + 255)/256, 256>>>(node_emb, bpool_g);
    k_bpool_c<<<(NN*DOUT + 255)/256, 256>>>(node_emb, bpool_c);
    k_hinit<<<(BB*NN*DOUT + 255)/256, 256>>>(init_state);

    // recurrence
    for (int t = 0; t < TT; t++) {
        k_adj   <<<dim3(NN/16, BB), 256>>>(t, node_emb, ne_tod, ne_dow);
        k_spmm_g<<<dim3(NN/64, BB), 128>>>(t);
        k_fc_g  <<<NN, 128>>>(t);
        k_spmm_c<<<dim3(NN/64, BB), 128>>>();
        k_fc_c  <<<NN, 128>>>(t);
    }

    // attention + h_last
    k_attn<<<dim3(NN/2, BB), 128>>>(WQ, bQ, WK, bK, WV, bV, out);
    if (out_size >= BB*TT*NN*DOUT + BB*NN*DOUT)
        k_hlast<<<(BB*NN*DOUT + 255)/256, 256>>>(out);
}

// round 14
// speedup vs baseline: 1.5974x; 1.5974x over previous
#include <cuda_runtime.h>

#define BB 16
#define TT 12
#define NN 1024
#define EMB 10
#define DIN 21      // 1 + 2*EMB
#define DOUT 64
#define FF 85       // DIN + DOUT
#define KF 170      // CHEB_K * FF
#define OG 128      // 2*DOUT
#define FG 96       // padded spmm-g cols: 85 data + 1 ones + 10 zero pad

// ---------------- device scratch (static, no allocation) ----------------
__device__ float g_cur[BB*TT*NN*DIN];
__device__ float g_Wg[NN*KF*OG];
__device__ float g_bg[NN*OG];
__device__ float g_Wc[NN*KF*DOUT];
__device__ float g_bc[NN*DOUT];
__device__ float g_h[BB*NN*DOUT];
__device__ float g_M[(size_t)BB*NN*NN];
__device__ float g_Yg[BB*NN*FG];
__device__ float g_Yc[BB*NN*DOUT];
__device__ float g_zh[BB*NN*DOUT];
__device__ float g_r [BB*NN*DOUT];
__device__ float g_seq[BB*TT*NN*DOUT];

// ---------------- one-time prep kernels ----------------
__global__ void k_embed(const float* __restrict__ x, const float* __restrict__ Wtod,
                        const float* __restrict__ btod, const float* __restrict__ Wdow,
                        const float* __restrict__ bdow) {
    int i = blockIdx.x * blockDim.x + threadIdx.x;
    if (i >= BB*TT*NN) return;
    float v   = x[i*3 + 0];
    int   tod = (int)x[i*3 + 1];
    int   dow = (int)x[i*3 + 2];
    float* c = g_cur + (size_t)i * DIN;
    c[0] = v;
    #pragma unroll
    for (int d = 0; d < EMB; d++) c[1 + d]       = Wtod[tod*EMB + d] + btod[d];
    #pragma unroll
    for (int d = 0; d < EMB; d++) c[1 + EMB + d] = Wdow[dow*EMB + d] + bdow[d];
}

__global__ void k_wpool_g(const float* __restrict__ E, const float* __restrict__ pool) {
    long i = (long)blockIdx.x * blockDim.x + threadIdx.x;
    if (i >= (long)NN*KF*OG) return;
    int o  = (int)(i % OG);
    int kf = (int)((i / OG) % KF);
    int n  = (int)(i / ((long)OG*KF));
    float s = 0.f;
    #pragma unroll
    for (int d = 0; d < EMB; d++)
        s += E[n*EMB + d] * pool[((long)d*KF + kf)*OG + o];
    g_Wg[i] = s;
}

__global__ void k_wpool_c(const float* __restrict__ E, const float* __restrict__ pool) {
    long i = (long)blockIdx.x * blockDim.x + threadIdx.x;
    if (i >= (long)NN*KF*DOUT) return;
    int o  = (int)(i % DOUT);
    int kf = (int)((i / DOUT) % KF);
    int n  = (int)(i / ((long)DOUT*KF));
    float s = 0.f;
    #pragma unroll
    for (int d = 0; d < EMB; d++)
        s += E[n*EMB + d] * pool[((long)d*KF + kf)*DOUT + o];
    g_Wc[i] = s;
}

__global__ void k_bpool_g(const float* __restrict__ E, const float* __restrict__ bpool) {
    int i = blockIdx.x * blockDim.x + threadIdx.x;
    if (i >= NN*OG) return;
    int o = i % OG, n = i / OG;
    float s = 0.f;
    #pragma unroll
    for (int d = 0; d < EMB; d++) s += E[n*EMB + d] * bpool[d*OG + o];
    g_bg[i] = s;
}

__global__ void k_bpool_c(const float* __restrict__ E, const float* __restrict__ bpool) {
    int i = blockIdx.x * blockDim.x + threadIdx.x;
    if (i >= NN*DOUT) return;
    int o = i % DOUT, n = i / DOUT;
    float s = 0.f;
    #pragma unroll
    for (int d = 0; d < EMB; d++) s += E[n*EMB + d] * bpool[d*DOUT + o];
    g_bc[i] = s;
}

__global__ void k_hinit(const float* __restrict__ init_state) {
    int i = blockIdx.x * blockDim.x + threadIdx.x;
    if (i < BB*NN*DOUT) g_h[i] = init_state[i];
}

// ---------------- per-step kernels ----------------
// M[b,n,m] = exp(relu(l) - rowmax(relu(l)))
__global__ void k_adj(int t, const float* __restrict__ E,
                      const float* __restrict__ ne1, const float* __restrict__ ne2) {
    __shared__ float Es[NN*EMB];
    __shared__ float Er[16][EMB];
    __shared__ float sred[16][8];
    __shared__ float rowmax[16];
    int b = blockIdx.y, n0 = blockIdx.x * 16, tid = threadIdx.x;

    for (int idx = tid; idx < NN*EMB; idx += 256) Es[idx] = E[idx];
    if (tid < 16*EMB) {
        int i = tid / EMB, d = tid % EMB;
        float s = ne1[(b*TT + t)*EMB + d] * ne2[(b*TT + t)*EMB + d];
        Er[i][d] = E[(n0 + i)*EMB + d] * s;
    }
    __syncthreads();

    float lmax[16];
    #pragma unroll
    for (int r = 0; r < 16; r++) lmax[r] = 0.f;
    for (int c = 0; c < 4; c++) {
        int m = c * 256 + tid;
        float em[EMB];
        #pragma unroll
        for (int d = 0; d < EMB; d++) em[d] = Es[m*EMB + d];
        #pragma unroll
        for (int r = 0; r < 16; r++) {
            float l = 0.f;
            #pragma unroll
            for (int d = 0; d < EMB; d++) l += em[d] * Er[r][d];
            lmax[r] = fmaxf(lmax[r], l);
        }
    }
    int lane = tid & 31, w = tid >> 5;
    #pragma unroll
    for (int r = 0; r < 16; r++) {
        float v = lmax[r];
        #pragma unroll
        for (int off = 16; off; off >>= 1) v = fmaxf(v, __shfl_xor_sync(0xffffffffu, v, off));
        if (lane == 0) sred[r][w] = v;
    }
    __syncthreads();
    if (tid < 16) {
        float v = sred[tid][0];
        #pragma unroll
        for (int w2 = 1; w2 < 8; w2++) v = fmaxf(v, sred[tid][w2]);
        rowmax[tid] = v;
    }
    __syncthreads();

    for (int c = 0; c < 4; c++) {
        int m = c * 256 + tid;
        float em[EMB];
        #pragma unroll
        for (int d = 0; d < EMB; d++) em[d] = Es[m*EMB + d];
        #pragma unroll
        for (int r = 0; r < 16; r++) {
            float l = 0.f;
            #pragma unroll
            for (int d = 0; d < EMB; d++) l += em[d] * Er[r][d];
            l = fmaxf(l, 0.f);
            g_M[((size_t)(b*NN) + (n0 + r))*NN + m] = __expf(l - rowmax[r]);
        }
    }
}

// Yg[b, n0..n0+63, 0:96] = M[b] @ [cur_t | h | 1 | 0pad]; double-buffered.
// 256 threads: tx = tid&15 (6 cols), ty = tid>>4 (4 rows). K-chunk 32.
__global__ void k_spmm_g(int t) {
    __shared__ float As[2][64][33];
    __shared__ float Xs[2][32][98];
    int b = blockIdx.y, n0 = blockIdx.x * 64, tid = threadIdx.x;
    int tx = tid & 15, ty = tid >> 4;

    float acc[4][6];
    #pragma unroll
    for (int i = 0; i < 4; i++)
        #pragma unroll
        for (int j = 0; j < 6; j++) acc[i][j] = 0.f;

    const float* curb = g_cur + (size_t)(b*TT + t) * NN * DIN;
    const float* hb   = g_h   + (size_t)b * NN * DOUT;
    const size_t mbase = (size_t)b * NN + n0;

    // invariant load coords: As 8/thread, Xs 12/thread
    const int a_r = tid >> 5, a_m = tid & 31;          // row += 8k
    const int x_mm = tid >> 3, x_f0 = (tid & 7) * 12;  // 12 consecutive f

    float ra[8], rx[12];
    // prologue: chunk 0
    #pragma unroll
    for (int k = 0; k < 8; k++) ra[k] = g_M[(mbase + a_r + 8*k)*NN + a_m];
    #pragma unroll
    for (int k = 0; k < 12; k++) {
        int f = x_f0 + k;
        rx[k] = (f < DIN) ? curb[x_mm*DIN + f]
              : (f < FF)  ? hb[x_mm*DOUT + (f - DIN)]
              : (f == FF) ? 1.f : 0.f;
    }
    #pragma unroll
    for (int k = 0; k < 8; k++) As[0][a_r + 8*k][a_m] = ra[k];
    #pragma unroll
    for (int k = 0; k < 12; k++) Xs[0][x_mm][x_f0 + k] = rx[k];
    __syncthreads();

    for (int c = 0; c < 32; c++) {
        int cur = c & 1;
        if (c + 1 < 32) {
            int m0 = (c + 1) * 32;
            #pragma unroll
            for (int k = 0; k < 8; k++) ra[k] = g_M[(mbase + a_r + 8*k)*NN + m0 + a_m];
            int m = m0 + x_mm;
            #pragma unroll
            for (int k = 0; k < 12; k++) {
                int f = x_f0 + k;
                rx[k] = (f < DIN) ? curb[m*DIN + f]
                      : (f < FF)  ? hb[m*DOUT + (f - DIN)]
                      : (f == FF) ? 1.f : 0.f;
            }
        }
        #pragma unroll 4
        for (int mm = 0; mm < 32; mm++) {
            float a[4], xv[6];
            #pragma unroll
            for (int i = 0; i < 4; i++) a[i] = As[cur][ty*4 + i][mm];
            #pragma unroll
            for (int j = 0; j < 6; j++) xv[j] = Xs[cur][mm][tx + 16*j];
            #pragma unroll
            for (int i = 0; i < 4; i++)
                #pragma unroll
                for (int j = 0; j < 6; j++) acc[i][j] = fmaf(a[i], xv[j], acc[i][j]);
        }
        if (c + 1 < 32) {
            __syncthreads();
            int nb = cur ^ 1;
            #pragma unroll
            for (int k = 0; k < 8; k++) As[nb][a_r + 8*k][a_m] = ra[k];
            #pragma unroll
            for (int k = 0; k < 12; k++) Xs[nb][x_mm][x_f0 + k] = rx[k];
            __syncthreads();
        }
    }
    #pragma unroll
    for (int i = 0; i < 4; i++)
        #pragma unroll
        for (int j = 0; j < 6; j++)
            g_Yg[((size_t)b*NN + n0 + ty*4 + i)*FG + tx + 16*j] = acc[i][j];
}

// Yc[b, n0..n0+63, 0:64] = M[b] @ zh; double-buffered, K-chunk 32.
__global__ void k_spmm_c() {
    __shared__ float As[2][64][33];
    __shared__ float Xs[2][32][66];
    int b = blockIdx.y, n0 = blockIdx.x * 64, tid = threadIdx.x;
    int tx = tid & 15, ty = tid >> 4;

    float acc[4][4];
    #pragma unroll
    for (int i = 0; i < 4; i++)
        #pragma unroll
        for (int j = 0; j < 4; j++) acc[i][j] = 0.f;

    const float* zb = g_zh + (size_t)b * NN * DOUT;
    const size_t mbase = (size_t)b * NN + n0;

    const int a_r = tid >> 5, a_m = tid & 31;
    const int x_mm = tid >> 3, x_f0 = (tid & 7) * 8;   // 8 consecutive f

    float ra[8], rx[8];
    #pragma unroll
    for (int k = 0; k < 8; k++) ra[k] = g_M[(mbase + a_r + 8*k)*NN + a_m];
    #pragma unroll
    for (int k = 0; k < 8; k++) rx[k] = zb[x_mm*DOUT + x_f0 + k];
    #pragma unroll
    for (int k = 0; k < 8; k++) As[0][a_r + 8*k][a_m] = ra[k];
    #pragma unroll
    for (int k = 0; k < 8; k++) Xs[0][x_mm][x_f0 + k] = rx[k];
    __syncthreads();

    for (int c = 0; c < 32; c++) {
        int cur = c & 1;
        if (c + 1 < 32) {
            int m0 = (c + 1) * 32;
            #pragma unroll
            for (int k = 0; k < 8; k++) ra[k] = g_M[(mbase + a_r + 8*k)*NN + m0 + a_m];
            #pragma unroll
            for (int k = 0; k < 8; k++) rx[k] = zb[(m0 + x_mm)*DOUT + x_f0 + k];
        }
        #pragma unroll 4
        for (int mm = 0; mm < 32; mm++) {
            float a[4], xv[4];
            #pragma unroll
            for (int i = 0; i < 4; i++) a[i] = As[cur][ty*4 + i][mm];
            #pragma unroll
            for (int j = 0; j < 4; j++) xv[j] = Xs[cur][mm][tx + 16*j];
            #pragma unroll
            for (int i = 0; i < 4; i++)
                #pragma unroll
                for (int j = 0; j < 4; j++) acc[i][j] = fmaf(a[i], xv[j], acc[i][j]);
        }
        if (c + 1 < 32) {
            __syncthreads();
            int nb = cur ^ 1;
            #pragma unroll
            for (int k = 0; k < 8; k++) As[nb][a_r + 8*k][a_m] = ra[k];
            #pragma unroll
            for (int k = 0; k < 8; k++) Xs[nb][x_mm][x_f0 + k] = rx[k];
            __syncthreads();
        }
    }
    #pragma unroll
    for (int i = 0; i < 4; i++)
        #pragma unroll
        for (int j = 0; j < 4; j++)
            g_Yc[((size_t)b*NN + n0 + ty*4 + i)*DOUT + tx + 16*j] = acc[i][j];
}

// gate FC: one CTA per node n, all 16 batches
__global__ void k_fc_g(int t) {
    __shared__ float xs[16][172];
    __shared__ float Ws[10][128];
    int n = blockIdx.x, tid = threadIdx.x;

    for (int idx = tid; idx < 16*KF; idx += 128) {
        int b = idx / KF, f = idx % KF;
        float v;
        if      (f < DIN) v = g_cur[((size_t)(b*TT + t)*NN + n)*DIN + f];
        else if (f < FF)  v = g_h[((size_t)b*NN + n)*DOUT + (f - DIN)];
        else {
            const float* y = g_Yg + ((size_t)b*NN + n)*FG;
            v = y[f - FF] / y[FF];
        }
        xs[b][f] = v;
    }
    __syncthreads();

    int og = tid & 31, bg = tid >> 5;
    float acc[4][4];
    #pragma unroll
    for (int i = 0; i < 4; i++)
        #pragma unroll
        for (int j = 0; j < 4; j++) acc[i][j] = 0.f;

    const float* Wn = g_Wg + (size_t)n * KF * OG;
    for (int fc = 0; fc < KF; fc += 10) {
        __syncthreads();
        for (int idx = tid; idx < 10*128; idx += 128)
            ((float*)Ws)[idx] = Wn[fc*128 + idx];
        __syncthreads();
        #pragma unroll
        for (int ff = 0; ff < 10; ff++) {
            float xv[4], wv[4];
            #pragma unroll
            for (int i = 0; i < 4; i++) xv[i] = xs[bg*4 + i][fc + ff];
            #pragma unroll
            for (int j = 0; j < 4; j++) wv[j] = Ws[ff][og + 32*j];
            #pragma unroll
            for (int i = 0; i < 4; i++)
                #pragma unroll
                for (int j = 0; j < 4; j++) acc[i][j] += xv[i] * wv[j];
        }
    }
    #pragma unroll
    for (int i = 0; i < 4; i++) {
        #pragma unroll
        for (int j = 0; j < 4; j++) {
            int b = bg*4 + i, o = og + 32*j;
            float v  = acc[i][j] + g_bg[n*OG + o];
            float sg = 1.f / (1.f + __expf(-v));
            size_t base = ((size_t)b*NN + n) * DOUT;
            if (o < DOUT) g_zh[base + o] = sg * g_h[base + o];
            else          g_r[base + (o - DOUT)] = sg;
        }
    }
}

// candidate FC + GRU update
__global__ void k_fc_c(int t) {
    __shared__ float xs[16][172];
    __shared__ float Ws[10][64];
    int n = blockIdx.x, tid = threadIdx.x;

    for (int idx = tid; idx < 16*KF; idx += 128) {
        int b = idx / KF, f = idx % KF;
        float v;
        if      (f < DIN) v = g_cur[((size_t)(b*TT + t)*NN + n)*DIN + f];
        else if (f < FF)  v = g_zh[((size_t)b*NN + n)*DOUT + (f - DIN)];
        else {
            int fp = f - FF;
            float num = (fp < DIN) ? g_Yg[((size_t)b*NN + n)*FG + fp]
                                   : g_Yc[((size_t)b*NN + n)*DOUT + (fp - DIN)];
            v = num / g_Yg[((size_t)b*NN + n)*FG + FF];
        }
        xs[b][f] = v;
    }
    __syncthreads();

    int og = tid & 31, bg = tid >> 5;
    float acc[4][2];
    #pragma unroll
    for (int i = 0; i < 4; i++) { acc[i][0] = 0.f; acc[i][1] = 0.f; }

    const float* Wn = g_Wc + (size_t)n * KF * DOUT;
    for (int fc = 0; fc < KF; fc += 10) {
        __syncthreads();
        for (int idx = tid; idx < 10*64; idx += 128)
            ((float*)Ws)[idx] = Wn[fc*64 + idx];
        __syncthreads();
        #pragma unroll
        for (int ff = 0; ff < 10; ff++) {
            float xv[4], wv[2];
            #pragma unroll
            for (int i = 0; i < 4; i++) xv[i] = xs[bg*4 + i][fc + ff];
            wv[0] = Ws[ff][og]; wv[1] = Ws[ff][og + 32];
            #pragma unroll
            for (int i = 0; i < 4; i++) {
                acc[i][0] += xv[i] * wv[0];
                acc[i][1] += xv[i] * wv[1];
            }
        }
    }
    #pragma unroll
    for (int i = 0; i < 4; i++) {
        #pragma unroll
        for (int j = 0; j < 2; j++) {
            int b = bg*4 + i, o = og + 32*j;
            float hc = tanhf(acc[i][j] + g_bc[n*DOUT + o]);
            size_t base = ((size_t)b*NN + n) * DOUT;
            float r    = g_r[base + o];
            float hold = g_h[base + o];
            float hn   = r * hold + (1.f - r) * hc;
            g_h[base + o] = hn;
            g_seq[((size_t)(b*TT + t)*NN + n)*DOUT + o] = hn;
        }
    }
}

// ---------------- temporal attention ----------------
__global__ void k_attn(const float* __restrict__ WQ, const float* __restrict__ bQ,
                       const float* __restrict__ WK, const float* __restrict__ bK,
                       const float* __restrict__ WV, const float* __restrict__ bV,
                       float* __restrict__ out) {
    __shared__ float xsm[2*TT*65];
    __shared__ float Qs [2*TT*65];
    __shared__ float Ks [2*TT*65];
    __shared__ float Vs [2*TT*65];
    __shared__ float P  [2*TT*TT];

    int b = blockIdx.y, n0 = blockIdx.x * 2;
    int tid = threadIdx.x, ng = tid >> 6, o = tid & 63, n = n0 + ng;

    #pragma unroll
    for (int t = 0; t < TT; t++)
        xsm[(ng*TT + t)*65 + o] = g_seq[((size_t)(b*TT + t)*NN + n)*DOUT + o];
    __syncthreads();

    float q[TT], k[TT], v[TT];
    {
        float bq = __ldg(bQ + o), bk = __ldg(bK + o), bv = __ldg(bV + o);
        #pragma unroll
        for (int t = 0; t < TT; t++) { q[t] = bq; k[t] = bk; v[t] = bv; }
    }
    for (int f = 0; f < 64; f++) {
        float wq = __ldg(WQ + f*64 + o);
        float wk = __ldg(WK + f*64 + o);
        float wv = __ldg(WV + f*64 + o);
        #pragma unroll
        for (int t = 0; t < TT; t++) {
            float xv = xsm[(ng*TT + t)*65 + f];
            q[t] += xv * wq; k[t] += xv * wk; v[t] += xv * wv;
        }
    }
    #pragma unroll
    for (int t = 0; t < TT; t++) {
        Qs[(ng*TT + t)*65 + o] = q[t];
        Ks[(ng*TT + t)*65 + o] = k[t];
        Vs[(ng*TT + t)*65 + o] = v[t];
    }
    __syncthreads();

    for (int p = o; p < TT*TT; p += 64) {
        int t1 = p / TT, s1 = p % TT;
        float s = 0.f;
        #pragma unroll
        for (int f = 0; f < 64; f++)
            s += Qs[(ng*TT + t1)*65 + f] * Ks[(ng*TT + s1)*65 + f];
        P[(ng*TT + t1)*TT + s1] = s * 0.125f;
    }
    __syncthreads();

    if (tid < 2*TT) {
        int ng2 = tid / TT, t1 = tid % TT;
        float* row = P + (ng2*TT + t1)*TT;
        float m = row[0];
        #pragma unroll
        for (int s = 1; s < TT; s++) m = fmaxf(m, row[s]);
        float sum = 0.f;
        #pragma unroll
        for (int s = 0; s < TT; s++) { float e = __expf(row[s] - m); row[s] = e; sum += e; }
        float inv = 1.f / sum;
        #pragma unroll
        for (int s = 0; s < TT; s++) row[s] *= inv;
    }
    __syncthreads();

    #pragma unroll
    for (int t1 = 0; t1 < TT; t1++) {
        float z = 0.f;
        #pragma unroll
        for (int s1 = 0; s1 < TT; s1++)
            z += P[(ng*TT + t1)*TT + s1] * Vs[(ng*TT + s1)*65 + o];
        out[((size_t)(b*TT + t1)*NN + n)*DOUT + o] = z;
    }
}

__global__ void k_hlast(float* __restrict__ out) {
    int i = blockIdx.x * blockDim.x + threadIdx.x;
    if (i < BB*NN*DOUT) out[(size_t)BB*TT*NN*DOUT + i] = g_h[i];
}

// ---------------- launch ----------------
extern "C" void kernel_launch(void* const* d_in, const int* in_sizes, int n_in,
                              void* d_out, int out_size) {
    const int esz[19] = {589824, 1048576, 1920, 1920, 10240, 480, 10, 70, 10,
                         4096, 64, 4096, 64, 4096, 64, 217600, 1280, 108800, 640};
    const float* p[19];
    int used[64];
    for (int i = 0; i < 64; i++) used[i] = 0;
    for (int j = 0; j < 19; j++) {
        p[j] = (j < n_in) ? (const float*)d_in[j] : (const float*)d_in[0];
        for (int i = 0; i < n_in && i < 64; i++) {
            if (!used[i] && in_sizes[i] == esz[j]) { p[j] = (const float*)d_in[i]; used[i] = 1; break; }
        }
    }
    const float* x          = p[0];
    const float* init_state = p[1];
    const float* ne_tod     = p[2];
    const float* ne_dow     = p[3];
    const float* node_emb   = p[4];
    const float* Wtod       = p[5];
    const float* btod       = p[6];
    const float* Wdow       = p[7];
    const float* bdow       = p[8];
    const float* WQ         = p[9];
    const float* bQ         = p[10];
    const float* WK         = p[11];
    const float* bK         = p[12];
    const float* WV         = p[13];
    const float* bV         = p[14];
    const float* Wpool_g    = p[15];
    const float* bpool_g    = p[16];
    const float* Wpool_c    = p[17];
    const float* bpool_c    = p[18];
    float* out = (float*)d_out;

    // prep
    k_embed<<<(BB*TT*NN + 255)/256, 256>>>(x, Wtod, btod, Wdow, bdow);
    k_wpool_g<<<(int)(((long)NN*KF*OG   + 255)/256), 256>>>(node_emb, Wpool_g);
    k_wpool_c<<<(int)(((long)NN*KF*DOUT + 255)/256), 256>>>(node_emb, Wpool_c);
    k_bpool_g<<<(NN*OG   + 255)/256, 256>>>(node_emb, bpool_g);
    k_bpool_c<<<(NN*DOUT + 255)/256, 256>>>(node_emb, bpool_c);
    k_hinit<<<(BB*NN*DOUT + 255)/256, 256>>>(init_state);

    // recurrence
    for (int t = 0; t < TT; t++) {
        k_adj   <<<dim3(NN/16, BB), 256>>>(t, node_emb, ne_tod, ne_dow);
        k_spmm_g<<<dim3(NN/64, BB), 256>>>(t);
        k_fc_g  <<<NN, 128>>>(t);
        k_spmm_c<<<dim3(NN/64, BB), 256>>>();
        k_fc_c  <<<NN, 128>>>(t);
    }

    // attention + h_last
    k_attn<<<dim3(NN/2, BB), 128>>>(WQ, bQ, WK, bK, WV, bV, out);
    if (out_size >= BB*TT*NN*DOUT + BB*NN*DOUT)
        k_hlast<<<(BB*NN*DOUT + 255)/256, 256>>>(out);
}

// round 15
// speedup vs baseline: 1.7585x; 1.1009x over previous
#include <cuda_runtime.h>

#define BB 16
#define TT 12
#define NN 1024
#define EMB 10
#define DIN 21      // 1 + 2*EMB
#define DOUT 64
#define FF 85       // DIN + DOUT
#define KF 170      // CHEB_K * FF
#define OG 128      // 2*DOUT
#define FG 96       // padded spmm-g cols: 85 data + 1 ones + 10 zero pad

// ---------------- device scratch (static, no allocation) ----------------
__device__ float g_cur[BB*TT*NN*DIN];
__device__ float g_Wg[NN*KF*OG];
__device__ float g_bg[NN*OG];
__device__ float g_Wc[NN*KF*DOUT];
__device__ float g_bc[NN*DOUT];
__device__ float g_h[BB*NN*DOUT];
__device__ float g_M[(size_t)BB*NN*NN];
__device__ float g_Yg[BB*NN*FG];
__device__ float g_Yc[BB*NN*DOUT];
__device__ float g_zh[BB*NN*DOUT];
__device__ float g_r [BB*NN*DOUT];
__device__ float g_seq[BB*TT*NN*DOUT];

// ---------------- one-time prep kernels ----------------
__global__ void k_embed(const float* __restrict__ x, const float* __restrict__ Wtod,
                        const float* __restrict__ btod, const float* __restrict__ Wdow,
                        const float* __restrict__ bdow) {
    int i = blockIdx.x * blockDim.x + threadIdx.x;
    if (i >= BB*TT*NN) return;
    float v   = x[i*3 + 0];
    int   tod = (int)x[i*3 + 1];
    int   dow = (int)x[i*3 + 2];
    float* c = g_cur + (size_t)i * DIN;
    c[0] = v;
    #pragma unroll
    for (int d = 0; d < EMB; d++) c[1 + d]       = Wtod[tod*EMB + d] + btod[d];
    #pragma unroll
    for (int d = 0; d < EMB; d++) c[1 + EMB + d] = Wdow[dow*EMB + d] + bdow[d];
}

__global__ void k_wpool_g(const float* __restrict__ E, const float* __restrict__ pool) {
    long i = (long)blockIdx.x * blockDim.x + threadIdx.x;
    if (i >= (long)NN*KF*OG) return;
    int o  = (int)(i % OG);
    int kf = (int)((i / OG) % KF);
    int n  = (int)(i / ((long)OG*KF));
    float s = 0.f;
    #pragma unroll
    for (int d = 0; d < EMB; d++)
        s += E[n*EMB + d] * pool[((long)d*KF + kf)*OG + o];
    g_Wg[i] = s;
}

__global__ void k_wpool_c(const float* __restrict__ E, const float* __restrict__ pool) {
    long i = (long)blockIdx.x * blockDim.x + threadIdx.x;
    if (i >= (long)NN*KF*DOUT) return;
    int o  = (int)(i % DOUT);
    int kf = (int)((i / DOUT) % KF);
    int n  = (int)(i / ((long)DOUT*KF));
    float s = 0.f;
    #pragma unroll
    for (int d = 0; d < EMB; d++)
        s += E[n*EMB + d] * pool[((long)d*KF + kf)*DOUT + o];
    g_Wc[i] = s;
}

__global__ void k_bpool_g(const float* __restrict__ E, const float* __restrict__ bpool) {
    int i = blockIdx.x * blockDim.x + threadIdx.x;
    if (i >= NN*OG) return;
    int o = i % OG, n = i / OG;
    float s = 0.f;
    #pragma unroll
    for (int d = 0; d < EMB; d++) s += E[n*EMB + d] * bpool[d*OG + o];
    g_bg[i] = s;
}

__global__ void k_bpool_c(const float* __restrict__ E, const float* __restrict__ bpool) {
    int i = blockIdx.x * blockDim.x + threadIdx.x;
    if (i >= NN*DOUT) return;
    int o = i % DOUT, n = i / DOUT;
    float s = 0.f;
    #pragma unroll
    for (int d = 0; d < EMB; d++) s += E[n*EMB + d] * bpool[d*DOUT + o];
    g_bc[i] = s;
}

__global__ void k_hinit(const float* __restrict__ init_state) {
    int i = blockIdx.x * blockDim.x + threadIdx.x;
    if (i < BB*NN*DOUT) g_h[i] = init_state[i];
}

// ---------------- per-step kernels ----------------
// M[b,n,m] = exp(relu(l) - rowmax(relu(l)))
__global__ void k_adj(int t, const float* __restrict__ E,
                      const float* __restrict__ ne1, const float* __restrict__ ne2) {
    __shared__ float Es[NN*EMB];
    __shared__ float Er[16][EMB];
    __shared__ float sred[16][8];
    __shared__ float rowmax[16];
    int b = blockIdx.y, n0 = blockIdx.x * 16, tid = threadIdx.x;

    for (int idx = tid; idx < NN*EMB; idx += 256) Es[idx] = E[idx];
    if (tid < 16*EMB) {
        int i = tid / EMB, d = tid % EMB;
        float s = ne1[(b*TT + t)*EMB + d] * ne2[(b*TT + t)*EMB + d];
        Er[i][d] = E[(n0 + i)*EMB + d] * s;
    }
    __syncthreads();

    float lmax[16];
    #pragma unroll
    for (int r = 0; r < 16; r++) lmax[r] = 0.f;
    for (int c = 0; c < 4; c++) {
        int m = c * 256 + tid;
        float em[EMB];
        #pragma unroll
        for (int d = 0; d < EMB; d++) em[d] = Es[m*EMB + d];
        #pragma unroll
        for (int r = 0; r < 16; r++) {
            float l = 0.f;
            #pragma unroll
            for (int d = 0; d < EMB; d++) l += em[d] * Er[r][d];
            lmax[r] = fmaxf(lmax[r], l);
        }
    }
    int lane = tid & 31, w = tid >> 5;
    #pragma unroll
    for (int r = 0; r < 16; r++) {
        float v = lmax[r];
        #pragma unroll
        for (int off = 16; off; off >>= 1) v = fmaxf(v, __shfl_xor_sync(0xffffffffu, v, off));
        if (lane == 0) sred[r][w] = v;
    }
    __syncthreads();
    if (tid < 16) {
        float v = sred[tid][0];
        #pragma unroll
        for (int w2 = 1; w2 < 8; w2++) v = fmaxf(v, sred[tid][w2]);
        rowmax[tid] = v;
    }
    __syncthreads();

    for (int c = 0; c < 4; c++) {
        int m = c * 256 + tid;
        float em[EMB];
        #pragma unroll
        for (int d = 0; d < EMB; d++) em[d] = Es[m*EMB + d];
        #pragma unroll
        for (int r = 0; r < 16; r++) {
            float l = 0.f;
            #pragma unroll
            for (int d = 0; d < EMB; d++) l += em[d] * Er[r][d];
            l = fmaxf(l, 0.f);
            g_M[((size_t)(b*NN) + (n0 + r))*NN + m] = __expf(l - rowmax[r]);
        }
    }
}

// Yg[b, n0..n0+63, 0:96] = M[b] @ [cur_t | h | 1 | 0pad]; double-buffered.
__global__ void k_spmm_g(int t) {
    __shared__ float As[2][64][33];
    __shared__ float Xs[2][32][98];
    int b = blockIdx.y, n0 = blockIdx.x * 64, tid = threadIdx.x;
    int tx = tid & 15, ty = tid >> 4;

    float acc[4][6];
    #pragma unroll
    for (int i = 0; i < 4; i++)
        #pragma unroll
        for (int j = 0; j < 6; j++) acc[i][j] = 0.f;

    const float* curb = g_cur + (size_t)(b*TT + t) * NN * DIN;
    const float* hb   = g_h   + (size_t)b * NN * DOUT;
    const size_t mbase = (size_t)b * NN + n0;

    const int a_r = tid >> 5, a_m = tid & 31;
    const int x_mm = tid >> 3, x_f0 = (tid & 7) * 12;

    float ra[8], rx[12];
    #pragma unroll
    for (int k = 0; k < 8; k++) ra[k] = g_M[(mbase + a_r + 8*k)*NN + a_m];
    #pragma unroll
    for (int k = 0; k < 12; k++) {
        int f = x_f0 + k;
        rx[k] = (f < DIN) ? curb[x_mm*DIN + f]
              : (f < FF)  ? hb[x_mm*DOUT + (f - DIN)]
              : (f == FF) ? 1.f : 0.f;
    }
    #pragma unroll
    for (int k = 0; k < 8; k++) As[0][a_r + 8*k][a_m] = ra[k];
    #pragma unroll
    for (int k = 0; k < 12; k++) Xs[0][x_mm][x_f0 + k] = rx[k];
    __syncthreads();

    for (int c = 0; c < 32; c++) {
        int cur = c & 1;
        if (c + 1 < 32) {
            int m0 = (c + 1) * 32;
            #pragma unroll
            for (int k = 0; k < 8; k++) ra[k] = g_M[(mbase + a_r + 8*k)*NN + m0 + a_m];
            int m = m0 + x_mm;
            #pragma unroll
            for (int k = 0; k < 12; k++) {
                int f = x_f0 + k;
                rx[k] = (f < DIN) ? curb[m*DIN + f]
                      : (f < FF)  ? hb[m*DOUT + (f - DIN)]
                      : (f == FF) ? 1.f : 0.f;
            }
        }
        #pragma unroll 4
        for (int mm = 0; mm < 32; mm++) {
            float a[4], xv[6];
            #pragma unroll
            for (int i = 0; i < 4; i++) a[i] = As[cur][ty*4 + i][mm];
            #pragma unroll
            for (int j = 0; j < 6; j++) xv[j] = Xs[cur][mm][tx + 16*j];
            #pragma unroll
            for (int i = 0; i < 4; i++)
                #pragma unroll
                for (int j = 0; j < 6; j++) acc[i][j] = fmaf(a[i], xv[j], acc[i][j]);
        }
        if (c + 1 < 32) {
            __syncthreads();
            int nb = cur ^ 1;
            #pragma unroll
            for (int k = 0; k < 8; k++) As[nb][a_r + 8*k][a_m] = ra[k];
            #pragma unroll
            for (int k = 0; k < 12; k++) Xs[nb][x_mm][x_f0 + k] = rx[k];
            __syncthreads();
        }
    }
    #pragma unroll
    for (int i = 0; i < 4; i++)
        #pragma unroll
        for (int j = 0; j < 6; j++)
            g_Yg[((size_t)b*NN + n0 + ty*4 + i)*FG + tx + 16*j] = acc[i][j];
}

// Yc[b, n0..n0+63, 0:64] = M[b] @ zh; double-buffered.
__global__ void k_spmm_c() {
    __shared__ float As[2][64][33];
    __shared__ float Xs[2][32][66];
    int b = blockIdx.y, n0 = blockIdx.x * 64, tid = threadIdx.x;
    int tx = tid & 15, ty = tid >> 4;

    float acc[4][4];
    #pragma unroll
    for (int i = 0; i < 4; i++)
        #pragma unroll
        for (int j = 0; j < 4; j++) acc[i][j] = 0.f;

    const float* zb = g_zh + (size_t)b * NN * DOUT;
    const size_t mbase = (size_t)b * NN + n0;

    const int a_r = tid >> 5, a_m = tid & 31;
    const int x_mm = tid >> 3, x_f0 = (tid & 7) * 8;

    float ra[8], rx[8];
    #pragma unroll
    for (int k = 0; k < 8; k++) ra[k] = g_M[(mbase + a_r + 8*k)*NN + a_m];
    #pragma unroll
    for (int k = 0; k < 8; k++) rx[k] = zb[x_mm*DOUT + x_f0 + k];
    #pragma unroll
    for (int k = 0; k < 8; k++) As[0][a_r + 8*k][a_m] = ra[k];
    #pragma unroll
    for (int k = 0; k < 8; k++) Xs[0][x_mm][x_f0 + k] = rx[k];
    __syncthreads();

    for (int c = 0; c < 32; c++) {
        int cur = c & 1;
        if (c + 1 < 32) {
            int m0 = (c + 1) * 32;
            #pragma unroll
            for (int k = 0; k < 8; k++) ra[k] = g_M[(mbase + a_r + 8*k)*NN + m0 + a_m];
            #pragma unroll
            for (int k = 0; k < 8; k++) rx[k] = zb[(m0 + x_mm)*DOUT + x_f0 + k];
        }
        #pragma unroll 4
        for (int mm = 0; mm < 32; mm++) {
            float a[4], xv[4];
            #pragma unroll
            for (int i = 0; i < 4; i++) a[i] = As[cur][ty*4 + i][mm];
            #pragma unroll
            for (int j = 0; j < 4; j++) xv[j] = Xs[cur][mm][tx + 16*j];
            #pragma unroll
            for (int i = 0; i < 4; i++)
                #pragma unroll
                for (int j = 0; j < 4; j++) acc[i][j] = fmaf(a[i], xv[j], acc[i][j]);
        }
        if (c + 1 < 32) {
            __syncthreads();
            int nb = cur ^ 1;
            #pragma unroll
            for (int k = 0; k < 8; k++) As[nb][a_r + 8*k][a_m] = ra[k];
            #pragma unroll
            for (int k = 0; k < 8; k++) Xs[nb][x_mm][x_f0 + k] = rx[k];
            __syncthreads();
        }
    }
    #pragma unroll
    for (int i = 0; i < 4; i++)
        #pragma unroll
        for (int j = 0; j < 4; j++)
            g_Yc[((size_t)b*NN + n0 + ty*4 + i)*DOUT + tx + 16*j] = acc[i][j];
}

// gate FC: one CTA per node n, all 16 batches; double-buffered W stream.
// KF=170 = 10 chunks of 17.
__global__ void k_fc_g(int t) {
    __shared__ float xs[16][172];
    __shared__ float Ws[2][17][128];
    int n = blockIdx.x, tid = threadIdx.x;

    const float* Wn = g_Wg + (size_t)n * KF * OG;

    // stage chunk 0 while also building xs
    #pragma unroll
    for (int k = 0; k < 17; k++) Ws[0][k][tid] = Wn[k*128 + tid];

    for (int idx = tid; idx < 16*KF; idx += 128) {
        int b = idx / KF, f = idx % KF;
        float v;
        if      (f < DIN) v = g_cur[((size_t)(b*TT + t)*NN + n)*DIN + f];
        else if (f < FF)  v = g_h[((size_t)b*NN + n)*DOUT + (f - DIN)];
        else {
            const float* y = g_Yg + ((size_t)b*NN + n)*FG;
            v = y[f - FF] / y[FF];
        }
        xs[b][f] = v;
    }
    __syncthreads();

    int og = tid & 31, bg = tid >> 5;
    float acc[4][4];
    #pragma unroll
    for (int i = 0; i < 4; i++)
        #pragma unroll
        for (int j = 0; j < 4; j++) acc[i][j] = 0.f;

    float rw[17];
    for (int c = 0; c < 10; c++) {
        int cur = c & 1;
        if (c + 1 < 10) {
            const float* Wc2 = Wn + (c + 1) * 17 * 128;
            #pragma unroll
            for (int k = 0; k < 17; k++) rw[k] = Wc2[k*128 + tid];
        }
        int fc = c * 17;
        #pragma unroll
        for (int ff = 0; ff < 17; ff++) {
            float xv[4], wv[4];
            #pragma unroll
            for (int i = 0; i < 4; i++) xv[i] = xs[bg*4 + i][fc + ff];
            #pragma unroll
            for (int j = 0; j < 4; j++) wv[j] = Ws[cur][ff][og + 32*j];
            #pragma unroll
            for (int i = 0; i < 4; i++)
                #pragma unroll
                for (int j = 0; j < 4; j++) acc[i][j] = fmaf(xv[i], wv[j], acc[i][j]);
        }
        if (c + 1 < 10) {
            __syncthreads();
            #pragma unroll
            for (int k = 0; k < 17; k++) Ws[cur ^ 1][k][tid] = rw[k];
            __syncthreads();
        }
    }
    #pragma unroll
    for (int i = 0; i < 4; i++) {
        #pragma unroll
        for (int j = 0; j < 4; j++) {
            int b = bg*4 + i, o = og + 32*j;
            float v  = acc[i][j] + g_bg[n*OG + o];
            float sg = 1.f / (1.f + __expf(-v));
            size_t base = ((size_t)b*NN + n) * DOUT;
            if (o < DOUT) g_zh[base + o] = sg * g_h[base + o];
            else          g_r[base + (o - DOUT)] = sg;
        }
    }
}

// candidate FC + GRU update; double-buffered W stream (chunks of 17 rows x 64).
__global__ void k_fc_c(int t) {
    __shared__ float xs[16][172];
    __shared__ float Ws[2][17*64];
    int n = blockIdx.x, tid = threadIdx.x;

    const float* Wn = g_Wc + (size_t)n * KF * DOUT;

    #pragma unroll
    for (int k = 0; k < 9; k++) {
        int idx = k*128 + tid;
        if (idx < 17*64) Ws[0][idx] = Wn[idx];
    }

    for (int idx = tid; idx < 16*KF; idx += 128) {
        int b = idx / KF, f = idx % KF;
        float v;
        if      (f < DIN) v = g_cur[((size_t)(b*TT + t)*NN + n)*DIN + f];
        else if (f < FF)  v = g_zh[((size_t)b*NN + n)*DOUT + (f - DIN)];
        else {
            int fp = f - FF;
            float num = (fp < DIN) ? g_Yg[((size_t)b*NN + n)*FG + fp]
                                   : g_Yc[((size_t)b*NN + n)*DOUT + (fp - DIN)];
            v = num / g_Yg[((size_t)b*NN + n)*FG + FF];
        }
        xs[b][f] = v;
    }
    __syncthreads();

    int og = tid & 31, bg = tid >> 5;
    float acc[4][2];
    #pragma unroll
    for (int i = 0; i < 4; i++) { acc[i][0] = 0.f; acc[i][1] = 0.f; }

    float rw[9];
    for (int c = 0; c < 10; c++) {
        int cur = c & 1;
        if (c + 1 < 10) {
            const float* Wc2 = Wn + (c + 1) * 17 * 64;
            #pragma unroll
            for (int k = 0; k < 9; k++) {
                int idx = k*128 + tid;
                rw[k] = (idx < 17*64) ? Wc2[idx] : 0.f;
            }
        }
        int fc = c * 17;
        #pragma unroll
        for (int ff = 0; ff < 17; ff++) {
            float xv[4], wv[2];
            #pragma unroll
            for (int i = 0; i < 4; i++) xv[i] = xs[bg*4 + i][fc + ff];
            wv[0] = Ws[cur][ff*64 + og]; wv[1] = Ws[cur][ff*64 + og + 32];
            #pragma unroll
            for (int i = 0; i < 4; i++) {
                acc[i][0] = fmaf(xv[i], wv[0], acc[i][0]);
                acc[i][1] = fmaf(xv[i], wv[1], acc[i][1]);
            }
        }
        if (c + 1 < 10) {
            __syncthreads();
            #pragma unroll
            for (int k = 0; k < 9; k++) {
                int idx = k*128 + tid;
                if (idx < 17*64) Ws[cur ^ 1][idx] = rw[k];
            }
            __syncthreads();
        }
    }
    #pragma unroll
    for (int i = 0; i < 4; i++) {
        #pragma unroll
        for (int j = 0; j < 2; j++) {
            int b = bg*4 + i, o = og + 32*j;
            float hc = tanhf(acc[i][j] + g_bc[n*DOUT + o]);
            size_t base = ((size_t)b*NN + n) * DOUT;
            float r    = g_r[base + o];
            float hold = g_h[base + o];
            float hn   = r * hold + (1.f - r) * hc;
            g_h[base + o] = hn;
            g_seq[((size_t)(b*TT + t)*NN + n)*DOUT + o] = hn;
        }
    }
}

// ---------------- temporal attention ----------------
__global__ void k_attn(const float* __restrict__ WQ, const float* __restrict__ bQ,
                       const float* __restrict__ WK, const float* __restrict__ bK,
                       const float* __restrict__ WV, const float* __restrict__ bV,
                       float* __restrict__ out) {
    __shared__ float xsm[2*TT*65];
    __shared__ float Qs [2*TT*65];
    __shared__ float Ks [2*TT*65];
    __shared__ float Vs [2*TT*65];
    __shared__ float P  [2*TT*TT];

    int b = blockIdx.y, n0 = blockIdx.x * 2;
    int tid = threadIdx.x, ng = tid >> 6, o = tid & 63, n = n0 + ng;

    #pragma unroll
    for (int t = 0; t < TT; t++)
        xsm[(ng*TT + t)*65 + o] = g_seq[((size_t)(b*TT + t)*NN + n)*DOUT + o];
    __syncthreads();

    float q[TT], k[TT], v[TT];
    {
        float bq = __ldg(bQ + o), bk = __ldg(bK + o), bv = __ldg(bV + o);
        #pragma unroll
        for (int t = 0; t < TT; t++) { q[t] = bq; k[t] = bk; v[t] = bv; }
    }
    for (int f = 0; f < 64; f++) {
        float wq = __ldg(WQ + f*64 + o);
        float wk = __ldg(WK + f*64 + o);
        float wv = __ldg(WV + f*64 + o);
        #pragma unroll
        for (int t = 0; t < TT; t++) {
            float xv = xsm[(ng*TT + t)*65 + f];
            q[t] += xv * wq; k[t] += xv * wk; v[t] += xv * wv;
        }
    }
    #pragma unroll
    for (int t = 0; t < TT; t++) {
        Qs[(ng*TT + t)*65 + o] = q[t];
        Ks[(ng*TT + t)*65 + o] = k[t];
        Vs[(ng*TT + t)*65 + o] = v[t];
    }
    __syncthreads();

    for (int p = o; p < TT*TT; p += 64) {
        int t1 = p / TT, s1 = p % TT;
        float s = 0.f;
        #pragma unroll
        for (int f = 0; f < 64; f++)
            s += Qs[(ng*TT + t1)*65 + f] * Ks[(ng*TT + s1)*65 + f];
        P[(ng*TT + t1)*TT + s1] = s * 0.125f;
    }
    __syncthreads();

    if (tid < 2*TT) {
        int ng2 = tid / TT, t1 = tid % TT;
        float* row = P + (ng2*TT + t1)*TT;
        float m = row[0];
        #pragma unroll
        for (int s = 1; s < TT; s++) m = fmaxf(m, row[s]);
        float sum = 0.f;
        #pragma unroll
        for (int s = 0; s < TT; s++) { float e = __expf(row[s] - m); row[s] = e; sum += e; }
        float inv = 1.f / sum;
        #pragma unroll
        for (int s = 0; s < TT; s++) row[s] *= inv;
    }
    __syncthreads();

    #pragma unroll
    for (int t1 = 0; t1 < TT; t1++) {
        float z = 0.f;
        #pragma unroll
        for (int s1 = 0; s1 < TT; s1++)
            z += P[(ng*TT + t1)*TT + s1] * Vs[(ng*TT + s1)*65 + o];
        out[((size_t)(b*TT + t1)*NN + n)*DOUT + o] = z;
    }
}

__global__ void k_hlast(float* __restrict__ out) {
    int i = blockIdx.x * blockDim.x + threadIdx.x;
    if (i < BB*NN*DOUT) out[(size_t)BB*TT*NN*DOUT + i] = g_h[i];
}

// ---------------- launch ----------------
extern "C" void kernel_launch(void* const* d_in, const int* in_sizes, int n_in,
                              void* d_out, int out_size) {
    const int esz[19] = {589824, 1048576, 1920, 1920, 10240, 480, 10, 70, 10,
                         4096, 64, 4096, 64, 4096, 64, 217600, 1280, 108800, 640};
    const float* p[19];
    int used[64];
    for (int i = 0; i < 64; i++) used[i] = 0;
    for (int j = 0; j < 19; j++) {
        p[j] = (j < n_in) ? (const float*)d_in[j] : (const float*)d_in[0];
        for (int i = 0; i < n_in && i < 64; i++) {
            if (!used[i] && in_sizes[i] == esz[j]) { p[j] = (const float*)d_in[i]; used[i] = 1; break; }
        }
    }
    const float* x          = p[0];
    const float* init_state = p[1];
    const float* ne_tod     = p[2];
    const float* ne_dow     = p[3];
    const float* node_emb   = p[4];
    const float* Wtod       = p[5];
    const float* btod       = p[6];
    const float* Wdow       = p[7];
    const float* bdow       = p[8];
    const float* WQ         = p[9];
    const float* bQ         = p[10];
    const float* WK         = p[11];
    const float* bK         = p[12];
    const float* WV         = p[13];
    const float* bV         = p[14];
    const float* Wpool_g    = p[15];
    const float* bpool_g    = p[16];
    const float* Wpool_c    = p[17];
    const float* bpool_c    = p[18];
    float* out = (float*)d_out;

    // prep
    k_embed<<<(BB*TT*NN + 255)/256, 256>>>(x, Wtod, btod, Wdow, bdow);
    k_wpool_g<<<(int)(((long)NN*KF*OG   + 255)/256), 256>>>(node_emb, Wpool_g);
    k_wpool_c<<<(int)(((long)NN*KF*DOUT + 255)/256), 256>>>(node_emb, Wpool_c);
    k_bpool_g<<<(NN*OG   + 255)/256, 256>>>(node_emb, bpool_g);
    k_bpool_c<<<(NN*DOUT + 255)/256, 256>>>(node_emb, bpool_c);
    k_hinit<<<(BB*NN*DOUT + 255)/256, 256>>>(init_state);

    // recurrence
    for (int t = 0; t < TT; t++) {
        k_adj   <<<dim3(NN/16, BB), 256>>>(t, node_emb, ne_tod, ne_dow);
        k_spmm_g<<<dim3(NN/64, BB), 256>>>(t);
        k_fc_g  <<<NN, 128>>>(t);
        k_spmm_c<<<dim3(NN/64, BB), 256>>>();
        k_fc_c  <<<NN, 128>>>(t);
    }

    // attention + h_last
    k_attn<<<dim3(NN/2, BB), 128>>>(WQ, bQ, WK, bK, WV, bV, out);
    if (out_size >= BB*TT*NN*DOUT + BB*NN*DOUT)
        k_hlast<<<(BB*NN*DOUT + 255)/256, 256>>>(out);
}

// round 17
// speedup vs baseline: 2.5411x; 1.4451x over previous
#include <cuda_runtime.h>

#define BB 16
#define TT 12
#define NN 1024
#define EMB 10
#define DIN 21      // 1 + 2*EMB
#define DOUT 64
#define FF 85       // DIN + DOUT
#define KF 170      // CHEB_K * FF
#define OG 128      // 2*DOUT
#define FG 96       // padded spmm-g cols: 85 data + 1 ones + 10 zero pad

// ---------------- device scratch (static, no allocation) ----------------
__device__ float g_cur[BB*TT*NN*DIN];
__device__ float g_Wg[NN*KF*OG];
__device__ float g_bg[NN*OG];
__device__ float g_Wc[NN*KF*DOUT];
__device__ float g_bc[NN*DOUT];
__device__ float g_h[BB*NN*DOUT];
__device__ float g_M[(size_t)BB*NN*NN];
__device__ float g_Yg[BB*NN*FG];
__device__ float g_Yc[BB*NN*DOUT];
__device__ float g_zh[BB*NN*DOUT];
__device__ float g_r [BB*NN*DOUT];
__device__ float g_seq[BB*TT*NN*DOUT];

// ---------------- helpers ----------------
__device__ __forceinline__ unsigned f2tf32(float f) {
    unsigned r;
    asm("cvt.rna.tf32.f32 %0, %1;" : "=r"(r) : "f"(f));
    return r;
}
__device__ __forceinline__ void mma_tf32(float c[4], unsigned a0, unsigned a1,
                                         unsigned a2, unsigned a3,
                                         unsigned b0, unsigned b1) {
    asm volatile(
        "mma.sync.aligned.m16n8k8.row.col.f32.tf32.tf32.f32 "
        "{%0,%1,%2,%3}, {%4,%5,%6,%7}, {%8,%9}, {%0,%1,%2,%3};"
        : "+f"(c[0]), "+f"(c[1]), "+f"(c[2]), "+f"(c[3])
        : "r"(a0), "r"(a1), "r"(a2), "r"(a3), "r"(b0), "r"(b1));
}

// ---------------- one-time prep kernels ----------------
__global__ void k_embed(const float* __restrict__ x, const float* __restrict__ Wtod,
                        const float* __restrict__ btod, const float* __restrict__ Wdow,
                        const float* __restrict__ bdow) {
    int i = blockIdx.x * blockDim.x + threadIdx.x;
    if (i >= BB*TT*NN) return;
    float v   = x[i*3 + 0];
    int   tod = (int)x[i*3 + 1];
    int   dow = (int)x[i*3 + 2];
    float* c = g_cur + (size_t)i * DIN;
    c[0] = v;
    #pragma unroll
    for (int d = 0; d < EMB; d++) c[1 + d]       = Wtod[tod*EMB + d] + btod[d];
    #pragma unroll
    for (int d = 0; d < EMB; d++) c[1 + EMB + d] = Wdow[dow*EMB + d] + bdow[d];
}

__global__ void k_wpool_g(const float* __restrict__ E, const float* __restrict__ pool) {
    long i = (long)blockIdx.x * blockDim.x + threadIdx.x;
    if (i >= (long)NN*KF*OG) return;
    int o  = (int)(i % OG);
    int kf = (int)((i / OG) % KF);
    int n  = (int)(i / ((long)OG*KF));
    float s = 0.f;
    #pragma unroll
    for (int d = 0; d < EMB; d++)
        s += E[n*EMB + d] * pool[((long)d*KF + kf)*OG + o];
    g_Wg[i] = s;
}

__global__ void k_wpool_c(const float* __restrict__ E, const float* __restrict__ pool) {
    long i = (long)blockIdx.x * blockDim.x + threadIdx.x;
    if (i >= (long)NN*KF*DOUT) return;
    int o  = (int)(i % DOUT);
    int kf = (int)((i / DOUT) % KF);
    int n  = (int)(i / ((long)DOUT*KF));
    float s = 0.f;
    #pragma unroll
    for (int d = 0; d < EMB; d++)
        s += E[n*EMB + d] * pool[((long)d*KF + kf)*DOUT + o];
    g_Wc[i] = s;
}

__global__ void k_bpool_g(const float* __restrict__ E, const float* __restrict__ bpool) {
    int i = blockIdx.x * blockDim.x + threadIdx.x;
    if (i >= NN*OG) return;
    int o = i % OG, n = i / OG;
    float s = 0.f;
    #pragma unroll
    for (int d = 0; d < EMB; d++) s += E[n*EMB + d] * bpool[d*OG + o];
    g_bg[i] = s;
}

__global__ void k_bpool_c(const float* __restrict__ E, const float* __restrict__ bpool) {
    int i = blockIdx.x * blockDim.x + threadIdx.x;
    if (i >= NN*DOUT) return;
    int o = i % DOUT, n = i / DOUT;
    float s = 0.f;
    #pragma unroll
    for (int d = 0; d < EMB; d++) s += E[n*EMB + d] * bpool[d*DOUT + o];
    g_bc[i] = s;
}

__global__ void k_hinit(const float* __restrict__ init_state) {
    int i = blockIdx.x * blockDim.x + threadIdx.x;
    if (i < BB*NN*DOUT) g_h[i] = init_state[i];
}

// ---------------- per-step kernels ----------------
// M[b,n,m] = exp(relu(l) - rowmax(relu(l)))
__global__ void k_adj(int t, const float* __restrict__ E,
                      const float* __restrict__ ne1, const float* __restrict__ ne2) {
    __shared__ float Es[NN*EMB];
    __shared__ float Er[16][EMB];
    __shared__ float sred[16][8];
    __shared__ float rowmax[16];
    int b = blockIdx.y, n0 = blockIdx.x * 16, tid = threadIdx.x;

    for (int idx = tid; idx < NN*EMB; idx += 256) Es[idx] = E[idx];
    if (tid < 16*EMB) {
        int i = tid / EMB, d = tid % EMB;
        float s = ne1[(b*TT + t)*EMB + d] * ne2[(b*TT + t)*EMB + d];
        Er[i][d] = E[(n0 + i)*EMB + d] * s;
    }
    __syncthreads();

    float lmax[16];
    #pragma unroll
    for (int r = 0; r < 16; r++) lmax[r] = 0.f;
    for (int c = 0; c < 4; c++) {
        int m = c * 256 + tid;
        float em[EMB];
        #pragma unroll
        for (int d = 0; d < EMB; d++) em[d] = Es[m*EMB + d];
        #pragma unroll
        for (int r = 0; r < 16; r++) {
            float l = 0.f;
            #pragma unroll
            for (int d = 0; d < EMB; d++) l += em[d] * Er[r][d];
            lmax[r] = fmaxf(lmax[r], l);
        }
    }
    int lane = tid & 31, w = tid >> 5;
    #pragma unroll
    for (int r = 0; r < 16; r++) {
        float v = lmax[r];
        #pragma unroll
        for (int off = 16; off; off >>= 1) v = fmaxf(v, __shfl_xor_sync(0xffffffffu, v, off));
        if (lane == 0) sred[r][w] = v;
    }
    __syncthreads();
    if (tid < 16) {
        float v = sred[tid][0];
        #pragma unroll
        for (int w2 = 1; w2 < 8; w2++) v = fmaxf(v, sred[tid][w2]);
        rowmax[tid] = v;
    }
    __syncthreads();

    for (int c = 0; c < 4; c++) {
        int m = c * 256 + tid;
        float em[EMB];
        #pragma unroll
        for (int d = 0; d < EMB; d++) em[d] = Es[m*EMB + d];
        #pragma unroll
        for (int r = 0; r < 16; r++) {
            float l = 0.f;
            #pragma unroll
            for (int d = 0; d < EMB; d++) l += em[d] * Er[r][d];
            l = fmaxf(l, 0.f);
            g_M[((size_t)(b*NN) + (n0 + r))*NN + m] = __expf(l - rowmax[r]);
        }
    }
}

// Yg = M @ [cur|h|1|0pad] via tf32 mma.sync. 256 thr = 8 warps (4m x 2n).
// As stride 36 (bank 4r+k conflict-free), Xs stride 104 (bank 8k+n conflict-free).
__global__ void k_spmm_g(int t) {
    __shared__ unsigned As[2][64*36];
    __shared__ unsigned Xs[2][32*104];
    int b = blockIdx.y, n0 = blockIdx.x * 64, tid = threadIdx.x;
    int wid = tid >> 5, lane = tid & 31;
    int grp = lane >> 2, tig = lane & 3;
    int rm = (wid & 3) * 16;        // warp row base
    int cn = (wid >> 2) * 48;       // warp col base

    float c6[6][4];
    #pragma unroll
    for (int i = 0; i < 6; i++)
        #pragma unroll
        for (int j = 0; j < 4; j++) c6[i][j] = 0.f;

    const float* curb = g_cur + (size_t)(b*TT + t) * NN * DIN;
    const float* hb   = g_h   + (size_t)b * NN * DOUT;
    const size_t mbase = (size_t)b * NN + n0;

    const int a_r = tid >> 5, a_m = tid & 31;
    const int x_mm = tid >> 3, x_f0 = (tid & 7) * 12;

    float ra[8], rx[12];
    #pragma unroll
    for (int k = 0; k < 8; k++) ra[k] = g_M[(mbase + a_r + 8*k)*NN + a_m];
    #pragma unroll
    for (int k = 0; k < 12; k++) {
        int f = x_f0 + k;
        rx[k] = (f < DIN) ? curb[x_mm*DIN + f]
              : (f < FF)  ? hb[x_mm*DOUT + (f - DIN)]
              : (f == FF) ? 1.f : 0.f;
    }
    #pragma unroll
    for (int k = 0; k < 8; k++) As[0][(a_r + 8*k)*36 + a_m] = f2tf32(ra[k]);
    #pragma unroll
    for (int k = 0; k < 12; k++) Xs[0][x_mm*104 + x_f0 + k] = f2tf32(rx[k]);
    __syncthreads();

    for (int c = 0; c < 32; c++) {
        int cur = c & 1;
        if (c + 1 < 32) {
            int m0 = (c + 1) * 32;
            #pragma unroll
            for (int k = 0; k < 8; k++) ra[k] = g_M[(mbase + a_r + 8*k)*NN + m0 + a_m];
            int m = m0 + x_mm;
            #pragma unroll
            for (int k = 0; k < 12; k++) {
                int f = x_f0 + k;
                rx[k] = (f < DIN) ? curb[m*DIN + f]
                      : (f < FF)  ? hb[m*DOUT + (f - DIN)]
                      : (f == FF) ? 1.f : 0.f;
            }
        }
        const unsigned* Ab = As[cur];
        const unsigned* Xb = Xs[cur];
        #pragma unroll
        for (int ks = 0; ks < 4; ks++) {
            int k0 = ks * 8;
            unsigned a0 = Ab[(rm + grp)*36     + k0 + tig];
            unsigned a1 = Ab[(rm + 8 + grp)*36 + k0 + tig];
            unsigned a2 = Ab[(rm + grp)*36     + k0 + 4 + tig];
            unsigned a3 = Ab[(rm + 8 + grp)*36 + k0 + 4 + tig];
            #pragma unroll
            for (int nt = 0; nt < 6; nt++) {
                int nc = cn + nt * 8;
                unsigned b0 = Xb[(k0 + tig)*104     + nc + grp];
                unsigned b1 = Xb[(k0 + 4 + tig)*104 + nc + grp];
                mma_tf32(c6[nt], a0, a1, a2, a3, b0, b1);
            }
        }
        if (c + 1 < 32) {
            __syncthreads();
            int nb = cur ^ 1;
            #pragma unroll
            for (int k = 0; k < 8; k++) As[nb][(a_r + 8*k)*36 + a_m] = f2tf32(ra[k]);
            #pragma unroll
            for (int k = 0; k < 12; k++) Xs[nb][x_mm*104 + x_f0 + k] = f2tf32(rx[k]);
            __syncthreads();
        }
    }
    // epilogue
    #pragma unroll
    for (int nt = 0; nt < 6; nt++) {
        int col = cn + nt*8 + 2*tig;
        size_t r0 = (size_t)b*NN + n0 + rm + grp;
        float2 v0 = make_float2(c6[nt][0], c6[nt][1]);
        float2 v1 = make_float2(c6[nt][2], c6[nt][3]);
        *(float2*)&g_Yg[r0*FG + col]       = v0;
        *(float2*)&g_Yg[(r0 + 8)*FG + col] = v1;
    }
}

// Yc = M @ zh via tf32 mma.sync. Xs stride 72 (bank 8k+n conflict-free).
__global__ void k_spmm_c() {
    __shared__ unsigned As[2][64*36];
    __shared__ unsigned Xs[2][32*72];
    int b = blockIdx.y, n0 = blockIdx.x * 64, tid = threadIdx.x;
    int wid = tid >> 5, lane = tid & 31;
    int grp = lane >> 2, tig = lane & 3;
    int rm = (wid & 3) * 16;
    int cn = (wid >> 2) * 32;

    float c4[4][4];
    #pragma unroll
    for (int i = 0; i < 4; i++)
        #pragma unroll
        for (int j = 0; j < 4; j++) c4[i][j] = 0.f;

    const float* zb = g_zh + (size_t)b * NN * DOUT;
    const size_t mbase = (size_t)b * NN + n0;

    const int a_r = tid >> 5, a_m = tid & 31;
    const int x_mm = tid >> 3, x_f0 = (tid & 7) * 8;

    float ra[8], rx[8];
    #pragma unroll
    for (int k = 0; k < 8; k++) ra[k] = g_M[(mbase + a_r + 8*k)*NN + a_m];
    #pragma unroll
    for (int k = 0; k < 8; k++) rx[k] = zb[x_mm*DOUT + x_f0 + k];
    #pragma unroll
    for (int k = 0; k < 8; k++) As[0][(a_r + 8*k)*36 + a_m] = f2tf32(ra[k]);
    #pragma unroll
    for (int k = 0; k < 8; k++) Xs[0][x_mm*72 + x_f0 + k] = f2tf32(rx[k]);
    __syncthreads();

    for (int c = 0; c < 32; c++) {
        int cur = c & 1;
        if (c + 1 < 32) {
            int m0 = (c + 1) * 32;
            #pragma unroll
            for (int k = 0; k < 8; k++) ra[k] = g_M[(mbase + a_r + 8*k)*NN + m0 + a_m];
            #pragma unroll
            for (int k = 0; k < 8; k++) rx[k] = zb[(m0 + x_mm)*DOUT + x_f0 + k];
        }
        const unsigned* Ab = As[cur];
        const unsigned* Xb = Xs[cur];
        #pragma unroll
        for (int ks = 0; ks < 4; ks++) {
            int k0 = ks * 8;
            unsigned a0 = Ab[(rm + grp)*36     + k0 + tig];
            unsigned a1 = Ab[(rm + 8 + grp)*36 + k0 + tig];
            unsigned a2 = Ab[(rm + grp)*36     + k0 + 4 + tig];
            unsigned a3 = Ab[(rm + 8 + grp)*36 + k0 + 4 + tig];
            #pragma unroll
            for (int nt = 0; nt < 4; nt++) {
                int nc = cn + nt * 8;
                unsigned b0 = Xb[(k0 + tig)*72     + nc + grp];
                unsigned b1 = Xb[(k0 + 4 + tig)*72 + nc + grp];
                mma_tf32(c4[nt], a0, a1, a2, a3, b0, b1);
            }
        }
        if (c + 1 < 32) {
            __syncthreads();
            int nb = cur ^ 1;
            #pragma unroll
            for (int k = 0; k < 8; k++) As[nb][(a_r + 8*k)*36 + a_m] = f2tf32(ra[k]);
            #pragma unroll
            for (int k = 0; k < 8; k++) Xs[nb][x_mm*72 + x_f0 + k] = f2tf32(rx[k]);
            __syncthreads();
        }
    }
    #pragma unroll
    for (int nt = 0; nt < 4; nt++) {
        int col = cn + nt*8 + 2*tig;
        size_t r0 = (size_t)b*NN + n0 + rm + grp;
        float2 v0 = make_float2(c4[nt][0], c4[nt][1]);
        float2 v1 = make_float2(c4[nt][2], c4[nt][3]);
        *(float2*)&g_Yc[r0*DOUT + col]       = v0;
        *(float2*)&g_Yc[(r0 + 8)*DOUT + col] = v1;
    }
}

// gate FC: one CTA per node n, all 16 batches; double-buffered W stream.
__global__ void k_fc_g(int t) {
    __shared__ float xs[16][172];
    __shared__ float Ws[2][17][128];
    int n = blockIdx.x, tid = threadIdx.x;

    const float* Wn = g_Wg + (size_t)n * KF * OG;

    #pragma unroll
    for (int k = 0; k < 17; k++) Ws[0][k][tid] = Wn[k*128 + tid];

    for (int idx = tid; idx < 16*KF; idx += 128) {
        int b = idx / KF, f = idx % KF;
        float v;
        if      (f < DIN) v = g_cur[((size_t)(b*TT + t)*NN + n)*DIN + f];
        else if (f < FF)  v = g_h[((size_t)b*NN + n)*DOUT + (f - DIN)];
        else {
            const float* y = g_Yg + ((size_t)b*NN + n)*FG;
            v = y[f - FF] / y[FF];
        }
        xs[b][f] = v;
    }
    __syncthreads();

    int og = tid & 31, bg = tid >> 5;
    float acc[4][4];
    #pragma unroll
    for (int i = 0; i < 4; i++)
        #pragma unroll
        for (int j = 0; j < 4; j++) acc[i][j] = 0.f;

    float rw[17];
    for (int c = 0; c < 10; c++) {
        int cur = c & 1;
        if (c + 1 < 10) {
            const float* Wc2 = Wn + (c + 1) * 17 * 128;
            #pragma unroll
            for (int k = 0; k < 17; k++) rw[k] = Wc2[k*128 + tid];
        }
        int fc = c * 17;
        #pragma unroll
        for (int ff = 0; ff < 17; ff++) {
            float xv[4], wv[4];
            #pragma unroll
            for (int i = 0; i < 4; i++) xv[i] = xs[bg*4 + i][fc + ff];
            #pragma unroll
            for (int j = 0; j < 4; j++) wv[j] = Ws[cur][ff][og + 32*j];
            #pragma unroll
            for (int i = 0; i < 4; i++)
                #pragma unroll
                for (int j = 0; j < 4; j++) acc[i][j] = fmaf(xv[i], wv[j], acc[i][j]);
        }
        if (c + 1 < 10) {
            __syncthreads();
            #pragma unroll
            for (int k = 0; k < 17; k++) Ws[cur ^ 1][k][tid] = rw[k];
            __syncthreads();
        }
    }
    #pragma unroll
    for (int i = 0; i < 4; i++) {
        #pragma unroll
        for (int j = 0; j < 4; j++) {
            int b = bg*4 + i, o = og + 32*j;
            float v  = acc[i][j] + g_bg[n*OG + o];
            float sg = 1.f / (1.f + __expf(-v));
            size_t base = ((size_t)b*NN + n) * DOUT;
            if (o < DOUT) g_zh[base + o] = sg * g_h[base + o];
            else          g_r[base + (o - DOUT)] = sg;
        }
    }
}

// candidate FC + GRU update; double-buffered W stream.
__global__ void k_fc_c(int t) {
    __shared__ float xs[16][172];
    __shared__ float Ws[2][17*64];
    int n = blockIdx.x, tid = threadIdx.x;

    const float* Wn = g_Wc + (size_t)n * KF * DOUT;

    #pragma unroll
    for (int k = 0; k < 9; k++) {
        int idx = k*128 + tid;
        if (idx < 17*64) Ws[0][idx] = Wn[idx];
    }

    for (int idx = tid; idx < 16*KF; idx += 128) {
        int b = idx / KF, f = idx % KF;
        float v;
        if      (f < DIN) v = g_cur[((size_t)(b*TT + t)*NN + n)*DIN + f];
        else if (f < FF)  v = g_zh[((size_t)b*NN + n)*DOUT + (f - DIN)];
        else {
            int fp = f - FF;
            float num = (fp < DIN) ? g_Yg[((size_t)b*NN + n)*FG + fp]
                                   : g_Yc[((size_t)b*NN + n)*DOUT + (fp - DIN)];
            v = num / g_Yg[((size_t)b*NN + n)*FG + FF];
        }
        xs[b][f] = v;
    }
    __syncthreads();

    int og = tid & 31, bg = tid >> 5;
    float acc[4][2];
    #pragma unroll
    for (int i = 0; i < 4; i++) { acc[i][0] = 0.f; acc[i][1] = 0.f; }

    float rw[9];
    for (int c = 0; c < 10; c++) {
        int cur = c & 1;
        if (c + 1 < 10) {
            const float* Wc2 = Wn + (c + 1) * 17 * 64;
            #pragma unroll
            for (int k = 0; k < 9; k++) {
                int idx = k*128 + tid;
                rw[k] = (idx < 17*64) ? Wc2[idx] : 0.f;
            }
        }
        int fc = c * 17;
        #pragma unroll
        for (int ff = 0; ff < 17; ff++) {
            float xv[4], wv[2];
            #pragma unroll
            for (int i = 0; i < 4; i++) xv[i] = xs[bg*4 + i][fc + ff];
            wv[0] = Ws[cur][ff*64 + og]; wv[1] = Ws[cur][ff*64 + og + 32];
            #pragma unroll
            for (int i = 0; i < 4; i++) {
                acc[i][0] = fmaf(xv[i], wv[0], acc[i][0]);
                acc[i][1] = fmaf(xv[i], wv[1], acc[i][1]);
            }
        }
        if (c + 1 < 10) {
            __syncthreads();
            #pragma unroll
            for (int k = 0; k < 9; k++) {
                int idx = k*128 + tid;
                if (idx < 17*64) Ws[cur ^ 1][idx] = rw[k];
            }
            __syncthreads();
        }
    }
    #pragma unroll
    for (int i = 0; i < 4; i++) {
        #pragma unroll
        for (int j = 0; j < 2; j++) {
            int b = bg*4 + i, o = og + 32*j;
            float hc = tanhf(acc[i][j] + g_bc[n*DOUT + o]);
            size_t base = ((size_t)b*NN + n) * DOUT;
            float r    = g_r[base + o];
            float hold = g_h[base + o];
            float hn   = r * hold + (1.f - r) * hc;
            g_h[base + o] = hn;
            g_seq[((size_t)(b*TT + t)*NN + n)*DOUT + o] = hn;
        }
    }
}

// ---------------- temporal attention ----------------
__global__ void k_attn(const float* __restrict__ WQ, const float* __restrict__ bQ,
                       const float* __restrict__ WK, const float* __restrict__ bK,
                       const float* __restrict__ WV, const float* __restrict__ bV,
                       float* __restrict__ out) {
    __shared__ float xsm[2*TT*65];
    __shared__ float Qs [2*TT*65];
    __shared__ float Ks [2*TT*65];
    __shared__ float Vs [2*TT*65];
    __shared__ float P  [2*TT*TT];

    int b = blockIdx.y, n0 = blockIdx.x * 2;
    int tid = threadIdx.x, ng = tid >> 6, o = tid & 63, n = n0 + ng;

    #pragma unroll
    for (int t = 0; t < TT; t++)
        xsm[(ng*TT + t)*65 + o] = g_seq[((size_t)(b*TT + t)*NN + n)*DOUT + o];
    __syncthreads();

    float q[TT], k[TT], v[TT];
    {
        float bq = __ldg(bQ + o), bk = __ldg(bK + o), bv = __ldg(bV + o);
        #pragma unroll
        for (int t = 0; t < TT; t++) { q[t] = bq; k[t] = bk; v[t] = bv; }
    }
    for (int f = 0; f < 64; f++) {
        float wq = __ldg(WQ + f*64 + o);
        float wk = __ldg(WK + f*64 + o);
        float wv = __ldg(WV + f*64 + o);
        #pragma unroll
        for (int t = 0; t < TT; t++) {
            float xv = xsm[(ng*TT + t)*65 + f];
            q[t] += xv * wq; k[t] += xv * wk; v[t] += xv * wv;
        }
    }
    #pragma unroll
    for (int t = 0; t < TT; t++) {
        Qs[(ng*TT + t)*65 + o] = q[t];
        Ks[(ng*TT + t)*65 + o] = k[t];
        Vs[(ng*TT + t)*65 + o] = v[t];
    }
    __syncthreads();

    for (int p = o; p < TT*TT; p += 64) {
        int t1 = p / TT, s1 = p % TT;
        float s = 0.f;
        #pragma unroll
        for (int f = 0; f < 64; f++)
            s += Qs[(ng*TT + t1)*65 + f] * Ks[(ng*TT + s1)*65 + f];
        P[(ng*TT + t1)*TT + s1] = s * 0.125f;
    }
    __syncthreads();

    if (tid < 2*TT) {
        int ng2 = tid / TT, t1 = tid % TT;
        float* row = P + (ng2*TT + t1)*TT;
        float m = row[0];
        #pragma unroll
        for (int s = 1; s < TT; s++) m = fmaxf(m, row[s]);
        float sum = 0.f;
        #pragma unroll
        for (int s = 0; s < TT; s++) { float e = __expf(row[s] - m); row[s] = e; sum += e; }
        float inv = 1.f / sum;
        #pragma unroll
        for (int s = 0; s < TT; s++) row[s] *= inv;
    }
    __syncthreads();

    #pragma unroll
    for (int t1 = 0; t1 < TT; t1++) {
        float z = 0.f;
        #pragma unroll
        for (int s1 = 0; s1 < TT; s1++)
            z += P[(ng*TT + t1)*TT + s1] * Vs[(ng*TT + s1)*65 + o];
        out[((size_t)(b*TT + t1)*NN + n)*DOUT + o] = z;
    }
}

__global__ void k_hlast(float* __restrict__ out) {
    int i = blockIdx.x * blockDim.x + threadIdx.x;
    if (i < BB*NN*DOUT) out[(size_t)BB*TT*NN*DOUT + i] = g_h[i];
}

// ---------------- launch ----------------
extern "C" void kernel_launch(void* const* d_in, const int* in_sizes, int n_in,
                              void* d_out, int out_size) {
    const int esz[19] = {589824, 1048576, 1920, 1920, 10240, 480, 10, 70, 10,
                         4096, 64, 4096, 64, 4096, 64, 217600, 1280, 108800, 640};
    const float* p[19];
    int used[64];
    for (int i = 0; i < 64; i++) used[i] = 0;
    for (int j = 0; j < 19; j++) {
        p[j] = (j < n_in) ? (const float*)d_in[j] : (const float*)d_in[0];
        for (int i = 0; i < n_in && i < 64; i++) {
            if (!used[i] && in_sizes[i] == esz[j]) { p[j] = (const float*)d_in[i]; used[i] = 1; break; }
        }
    }
    const float* x          = p[0];
    const float* init_state = p[1];
    const float* ne_tod     = p[2];
    const float* ne_dow     = p[3];
    const float* node_emb   = p[4];
    const float* Wtod       = p[5];
    const float* btod       = p[6];
    const float* Wdow       = p[7];
    const float* bdow       = p[8];
    const float* WQ         = p[9];
    const float* bQ         = p[10];
    const float* WK         = p[11];
    const float* bK         = p[12];
    const float* WV         = p[13];
    const float* bV         = p[14];
    const float* Wpool_g    = p[15];
    const float* bpool_g    = p[16];
    const float* Wpool_c    = p[17];
    const float* bpool_c    = p[18];
    float* out = (float*)d_out;

    // prep
    k_embed<<<(BB*TT*NN + 255)/256, 256>>>(x, Wtod, btod, Wdow, bdow);
    k_wpool_g<<<(int)(((long)NN*KF*OG   + 255)/256), 256>>>(node_emb, Wpool_g);
    k_wpool_c<<<(int)(((long)NN*KF*DOUT + 255)/256), 256>>>(node_emb, Wpool_c);
    k_bpool_g<<<(NN*OG   + 255)/256, 256>>>(node_emb, bpool_g);
    k_bpool_c<<<(NN*DOUT + 255)/256, 256>>>(node_emb, bpool_c);
    k_hinit<<<(BB*NN*DOUT + 255)/256, 256>>>(init_state);

    // recurrence
    for (int t = 0; t < TT; t++) {
        k_adj   <<<dim3(NN/16, BB), 256>>>(t, node_emb, ne_tod, ne_dow);
        k_spmm_g<<<dim3(NN/64, BB), 256>>>(t);
        k_fc_g  <<<NN, 128>>>(t);
        k_spmm_c<<<dim3(NN/64, BB), 256>>>();
        k_fc_c  <<<NN, 128>>>(t);
    }

    // attention + h_last
    k_attn<<<dim3(NN/2, BB), 128>>>(WQ, bQ, WK, bK, WV, bV, out);
    if (out_size >= BB*TT*NN*DOUT + BB*NN*DOUT)
        k_hlast<<<(BB*NN*DOUT + 255)/256, 256>>>(out);
}